// round 2
// baseline (speedup 1.0000x reference)
#include <cuda_runtime.h>
#include <cuda_bf16.h>
#include <math.h>

// ---------------- problem constants ----------------
#define BB    2
#define SS    2048
#define DIM   2048
#define HH    16
#define NOPE  128
#define ROPE  64
#define QKHD  192     // NOPE + ROPE
#define VHD   128
#define KVRANK 512
#define ROWS  (BB*SS)           // 4096
#define QCOLS (HH*QKHD)         // 3072
#define KVCOLS (KVRANK + HH*ROPE) // 1536

// ---------------- scratch (device globals; no allocation allowed) ----------
__device__ float g_q  [ROWS * QCOLS];        // q proj, rope applied in place -> Q [b,s,h,192]
__device__ float g_kv [ROWS * KVCOLS];       // kv_a proj (first 1024 cols = k_rope, last 512 = latent)
__device__ float g_c  [ROWS * KVRANK];       // layernormed latent
__device__ float g_kn [ROWS * HH * NOPE];    // k_nope (B,S,2048)
__device__ float g_v  [ROWS * HH * VHD];     // v  [b,s,h,128]
__device__ float g_K  [ROWS * HH * QKHD];    // assembled K [b,s,h,192] (reference reshape semantics)
__device__ float g_O  [ROWS * HH * VHD];     // attention out [b,s,h,128]

// ---------------- generic fp32 GEMM: C = A[MxK] * B[KxN] + bias ------------
// 128x128 tile, BK=8, 256 threads, 8x8 register microtile.
__global__ void gemm_bias_kernel(const float* __restrict__ A,
                                 const float* __restrict__ B,
                                 const float* __restrict__ bias,
                                 float* __restrict__ C,
                                 int M, int N, int K)
{
    const int BM = 128, BN = 128, BK = 8;
    __shared__ float As[BK][BM];
    __shared__ float Bs[BK][BN];

    const int tid = threadIdx.x;
    const int tx = tid % 16;
    const int ty = tid / 16;
    const int row0 = blockIdx.y * BM;
    const int col0 = blockIdx.x * BN;

    const int ar = tid >> 1;            // 0..127
    const int ac = (tid & 1) * 4;       // 0 or 4
    const int br = tid >> 5;            // 0..7
    const int bc = (tid & 31) * 4;      // 0..124

    float acc[8][8];
    #pragma unroll
    for (int i = 0; i < 8; i++)
        #pragma unroll
        for (int j = 0; j < 8; j++) acc[i][j] = 0.f;

    for (int k0 = 0; k0 < K; k0 += BK) {
        float4 av = *(const float4*)&A[(size_t)(row0 + ar) * K + k0 + ac];
        As[ac + 0][ar] = av.x;
        As[ac + 1][ar] = av.y;
        As[ac + 2][ar] = av.z;
        As[ac + 3][ar] = av.w;
        float4 bv = *(const float4*)&B[(size_t)(k0 + br) * N + col0 + bc];
        *(float4*)&Bs[br][bc] = bv;
        __syncthreads();

        #pragma unroll
        for (int kk = 0; kk < BK; kk++) {
            float a[8], b[8];
            *(float4*)&a[0] = *(const float4*)&As[kk][ty * 8];
            *(float4*)&a[4] = *(const float4*)&As[kk][ty * 8 + 4];
            *(float4*)&b[0] = *(const float4*)&Bs[kk][tx * 8];
            *(float4*)&b[4] = *(const float4*)&Bs[kk][tx * 8 + 4];
            #pragma unroll
            for (int i = 0; i < 8; i++)
                #pragma unroll
                for (int j = 0; j < 8; j++)
                    acc[i][j] += a[i] * b[j];
        }
        __syncthreads();
    }

    #pragma unroll
    for (int i = 0; i < 8; i++) {
        int r = row0 + ty * 8 + i;
        #pragma unroll
        for (int j = 0; j < 8; j += 4) {
            int c = col0 + tx * 8 + j;
            float4 o;
            o.x = acc[i][j + 0] + bias[c + 0];
            o.y = acc[i][j + 1] + bias[c + 1];
            o.z = acc[i][j + 2] + bias[c + 2];
            o.w = acc[i][j + 3] + bias[c + 3];
            *(float4*)&C[(size_t)r * N + c] = o;
        }
    }
}

// ---------------- LayerNorm over the 512-wide latent slice ------------------
__global__ void ln_kernel(const float* __restrict__ kv,
                          const float* __restrict__ gamma,
                          const float* __restrict__ beta,
                          float* __restrict__ out)
{
    const int row = blockIdx.x;
    const float* src = kv + (size_t)row * KVCOLS + HH * ROPE;
    float* dst = out + (size_t)row * KVRANK;
    const int tid = threadIdx.x;   // 128 threads

    float v[4];
    float s = 0.f, s2 = 0.f;
    #pragma unroll
    for (int i = 0; i < 4; i++) {
        v[i] = src[tid + i * 128];
        s += v[i];
        s2 += v[i] * v[i];
    }
    __shared__ float rs[128], rs2[128];
    rs[tid] = s; rs2[tid] = s2;
    __syncthreads();
    for (int o = 64; o > 0; o >>= 1) {
        if (tid < o) { rs[tid] += rs[tid + o]; rs2[tid] += rs2[tid + o]; }
        __syncthreads();
    }
    float mean = rs[0] * (1.f / 512.f);
    float var  = rs2[0] * (1.f / 512.f) - mean * mean;
    float rstd = rsqrtf(var + 1e-5f);
    #pragma unroll
    for (int i = 0; i < 4; i++) {
        int c = tid + i * 128;
        dst[c] = (v[i] - mean) * rstd * gamma[c] + beta[c];
    }
}

// ---------------- RoPE + K assembly (REFERENCE reshape semantics) -----------
// concat_vec = [k_nope (2048) || k_rope (1024)]; head h = concat_vec[h*192 : +192];
// rope applied to dims [128,192) of each head AFTER that reshape.
// one thread per (row, h, pair p in [0,32))
__global__ void rope_assemble_kernel(float* __restrict__ q,
                                     const float* __restrict__ kv,
                                     const float* __restrict__ knope,
                                     const float* __restrict__ cosT,
                                     const float* __restrict__ sinT,
                                     float* __restrict__ Kout)
{
    int idx = blockIdx.x * blockDim.x + threadIdx.x;
    if (idx >= ROWS * HH * 32) return;
    int p   = idx & 31;
    int h   = (idx >> 5) & 15;
    int row = idx >> 9;
    int s   = row & (SS - 1);

    float cv = cosT[s * 32 + p];
    float sv = sinT[s * 32 + p];

    // q rope (in place) — q is a direct reshape, per-head layout is natural
    size_t qb = (size_t)row * QCOLS + h * QKHD + NOPE + 2 * p;
    float a = q[qb], b = q[qb + 1];
    q[qb]     = a * cv - b * sv;
    q[qb + 1] = a * sv + b * cv;

    const float* knr = knope + (size_t)row * (HH * NOPE);   // 2048 values
    const float* krr = kv + (size_t)row * KVCOLS;            // first 1024 cols = k_rope
    size_t ko = ((size_t)row * HH + h) * QKHD;

    // nope part of head h: dims [0,128), thread handles d = p*4 .. p*4+3
    {
        int g = h * QKHD + p * 4;        // global concat index (multiple of 4)
        float4 nv;
        if (g < HH * NOPE) nv = *(const float4*)&knr[g];
        else               nv = *(const float4*)&krr[g - HH * NOPE];
        *(float4*)&Kout[ko + p * 4] = nv;
    }

    // rope part of head h: dims d = 128+2p, 129+2p
    {
        int g = h * QKHD + NOPE + 2 * p;   // even; pair never straddles 2048
        float ka, kb;
        if (g < HH * NOPE) { ka = knr[g];             kb = knr[g + 1]; }
        else               { ka = krr[g - HH * NOPE]; kb = krr[g - HH * NOPE + 1]; }
        Kout[ko + NOPE + 2 * p]     = ka * cv - kb * sv;
        Kout[ko + NOPE + 2 * p + 1] = ka * sv + kb * cv;
    }
}

// ---------------- causal flash attention (fp32) -----------------------------
// Q,K: [b,s,h,192]  V,O: [b,s,h,128].  BQ=BK=32 tiles, 256 threads.
#define BQ 32
#define BKT 32
#define QPAD 193           // conflict-free row-major Q
#define KTP 33             // K stored transposed [192][33]
#define VPAD 132
#define PPAD 33

__global__ void attn_kernel(const float* __restrict__ Q,
                            const float* __restrict__ Kf,
                            const float* __restrict__ V,
                            float* __restrict__ O)
{
    const int q0 = blockIdx.x * BQ;
    const int h  = blockIdx.y;
    const int b  = blockIdx.z;

    extern __shared__ float sm[];
    float* Qs = sm;                      // 32*193
    float* Ks = Qs + BQ * QPAD;          // 192*33 (transposed)
    float* Vs = Ks + QKHD * KTP;         // 32*132
    float* Ps = Vs + BKT * VPAD;         // 32*33

    const int tid = threadIdx.x;
    const int tx = tid & 7;
    const int ty = tid >> 3;
    const float scale = 0.07216878364870322f;   // 192^-0.5

    // load Q tile
    for (int i = tid; i < BQ * QKHD; i += 256) {
        int r = i / QKHD, d = i % QKHD;
        Qs[r * QPAD + d] = Q[(((size_t)(b * SS + q0 + r) * HH) + h) * QKHD + d];
    }

    float m = -INFINITY, l = 0.f;
    float acc[16];
    #pragma unroll
    for (int i = 0; i < 16; i++) acc[i] = 0.f;

    const int jend = q0 / BKT;   // inclusive (covers diagonal block)
    for (int j = 0; j <= jend; j++) {
        const int k0 = j * BKT;
        __syncthreads();  // previous iteration finished reading Ks/Vs/Ps
        for (int i = tid; i < BKT * QKHD; i += 256) {
            int r = i / QKHD, d = i % QKHD;
            Ks[d * KTP + r] = Kf[(((size_t)(b * SS + k0 + r) * HH) + h) * QKHD + d];
        }
        for (int i = tid; i < BKT * VHD; i += 256) {
            int r = i / VHD, d = i % VHD;
            Vs[r * VPAD + d] = V[(((size_t)(b * SS + k0 + r) * HH) + h) * VHD + d];
        }
        __syncthreads();

        // scores
        float s0 = 0.f, s1 = 0.f, s2 = 0.f, s3 = 0.f;
        const float* qrow = &Qs[ty * QPAD];
        const int cb = tx * 4;
        #pragma unroll 4
        for (int d = 0; d < QKHD; d++) {
            float qv = qrow[d];
            const float* kc = &Ks[d * KTP + cb];
            s0 += qv * kc[0];
            s1 += qv * kc[1];
            s2 += qv * kc[2];
            s3 += qv * kc[3];
        }
        float s[4] = { s0 * scale, s1 * scale, s2 * scale, s3 * scale };
        const int qi = q0 + ty;
        #pragma unroll
        for (int c4 = 0; c4 < 4; c4++)
            if (k0 + cb + c4 > qi) s[c4] = -INFINITY;

        // row max over 8 threads (lanes of a row are 8 consecutive lanes)
        float mloc = fmaxf(fmaxf(s[0], s[1]), fmaxf(s[2], s[3]));
        mloc = fmaxf(mloc, __shfl_xor_sync(0xffffffffu, mloc, 1));
        mloc = fmaxf(mloc, __shfl_xor_sync(0xffffffffu, mloc, 2));
        mloc = fmaxf(mloc, __shfl_xor_sync(0xffffffffu, mloc, 4));
        float mnew = fmaxf(m, mloc);

        float p[4], lloc = 0.f;
        #pragma unroll
        for (int c4 = 0; c4 < 4; c4++) {
            p[c4] = __expf(s[c4] - mnew);   // exp(-inf) = 0 for masked
            lloc += p[c4];
        }
        lloc += __shfl_xor_sync(0xffffffffu, lloc, 1);
        lloc += __shfl_xor_sync(0xffffffffu, lloc, 2);
        lloc += __shfl_xor_sync(0xffffffffu, lloc, 4);

        float alpha = __expf(m - mnew);     // m=-inf first iter -> 0
        m = mnew;
        l = l * alpha + lloc;

        #pragma unroll
        for (int c4 = 0; c4 < 4; c4++) Ps[ty * PPAD + cb + c4] = p[c4];
        #pragma unroll
        for (int i = 0; i < 16; i++) acc[i] *= alpha;
        __syncthreads();

        // PV
        const int vb = tx * 16;
        #pragma unroll 4
        for (int k = 0; k < BKT; k++) {
            float pv = Ps[ty * PPAD + k];
            const float* vr = &Vs[k * VPAD + vb];
            #pragma unroll
            for (int i = 0; i < 16; i++) acc[i] += pv * vr[i];
        }
    }

    float invl = 1.f / l;
    size_t ob = (((size_t)(b * SS + q0 + ty) * HH) + h) * VHD + tx * 16;
    #pragma unroll
    for (int i = 0; i < 16; i += 4) {
        float4 o;
        o.x = acc[i + 0] * invl;
        o.y = acc[i + 1] * invl;
        o.z = acc[i + 2] * invl;
        o.w = acc[i + 3] * invl;
        *(float4*)&O[ob + i] = o;
    }
}

#define ATTN_SMEM ((BQ*QPAD + QKHD*KTP + BKT*VPAD + BQ*PPAD) * sizeof(float))

// ---------------- launch -----------------------------------------------------
extern "C" void kernel_launch(void* const* d_in, const int* in_sizes, int n_in,
                              void* d_out, int out_size)
{
    const float* x       = (const float*)d_in[0];
    const float* wq_w    = (const float*)d_in[1];
    const float* wq_b    = (const float*)d_in[2];
    const float* wkv_a_w = (const float*)d_in[3];
    const float* wkv_a_b = (const float*)d_in[4];
    const float* kvn_g   = (const float*)d_in[5];
    const float* kvn_b   = (const float*)d_in[6];
    const float* wk_w    = (const float*)d_in[7];
    const float* wk_b    = (const float*)d_in[8];
    const float* wv_w    = (const float*)d_in[9];
    const float* wv_b    = (const float*)d_in[10];
    const float* wo_w    = (const float*)d_in[11];
    const float* wo_b    = (const float*)d_in[12];
    const float* cosT    = (const float*)d_in[13];
    const float* sinT    = (const float*)d_in[14];
    float* out = (float*)d_out;

    float *gq, *gkv, *gc, *gkn, *gv, *gK, *gO;
    cudaGetSymbolAddress((void**)&gq,  g_q);
    cudaGetSymbolAddress((void**)&gkv, g_kv);
    cudaGetSymbolAddress((void**)&gc,  g_c);
    cudaGetSymbolAddress((void**)&gkn, g_kn);
    cudaGetSymbolAddress((void**)&gv,  g_v);
    cudaGetSymbolAddress((void**)&gK,  g_K);
    cudaGetSymbolAddress((void**)&gO,  g_O);

    // 1) q = x @ wq_w + b     [4096,3072] K=2048
    gemm_bias_kernel<<<dim3(QCOLS/128, ROWS/128), 256>>>(x, wq_w, wq_b, gq, ROWS, QCOLS, DIM);
    // 2) kv = x @ wkv_a_w + b [4096,1536] K=2048
    gemm_bias_kernel<<<dim3(KVCOLS/128, ROWS/128), 256>>>(x, wkv_a_w, wkv_a_b, gkv, ROWS, KVCOLS, DIM);
    // 3) layernorm latent
    ln_kernel<<<ROWS, 128>>>(gkv, kvn_g, kvn_b, gc);
    // 4) k_nope = c @ wk_w + b [4096,2048] K=512
    gemm_bias_kernel<<<dim3((HH*NOPE)/128, ROWS/128), 256>>>(gc, wk_w, wk_b, gkn, ROWS, HH*NOPE, KVRANK);
    // 5) v = c @ wv_w + b
    gemm_bias_kernel<<<dim3((HH*VHD)/128, ROWS/128), 256>>>(gc, wv_w, wv_b, gv, ROWS, HH*VHD, KVRANK);
    // 6) rope + assemble K (reference reshape semantics)
    {
        int total = ROWS * HH * 32;
        rope_assemble_kernel<<<(total + 255) / 256, 256>>>(gq, gkv, gkn, cosT, sinT, gK);
    }
    // 7) attention
    cudaFuncSetAttribute(attn_kernel, cudaFuncAttributeMaxDynamicSharedMemorySize, (int)ATTN_SMEM);
    attn_kernel<<<dim3(SS/BQ, HH, BB), 256, ATTN_SMEM>>>(gq, gK, gv, gO);
    // 8) out = O @ wo_w + b
    gemm_bias_kernel<<<dim3(DIM/128, ROWS/128), 256>>>(gO, wo_w, wo_b, out, ROWS, DIM, HH*VHD);
}

// round 3
// speedup vs baseline: 1.8922x; 1.8922x over previous
#include <cuda_runtime.h>
#include <cuda_bf16.h>
#include <math.h>

// ---------------- problem constants ----------------
#define BB    2
#define SS    2048
#define DIM   2048
#define HH    16
#define NOPE  128
#define ROPE  64
#define QKHD  192     // NOPE + ROPE
#define VHD   128
#define KVRANK 512
#define ROWS  (BB*SS)           // 4096
#define QCOLS (HH*QKHD)         // 3072
#define KVCOLS (KVRANK + HH*ROPE) // 1536

// ---------------- scratch (device globals; no allocation allowed) ----------
__device__ float g_q  [ROWS * QCOLS];        // q proj, rope applied in place -> Q [b,s,h,192]
__device__ float g_kv [ROWS * KVCOLS];       // kv_a proj (first 1024 cols = k_rope, last 512 = latent)
__device__ float g_c  [ROWS * KVRANK];       // layernormed latent
__device__ float g_kn [ROWS * HH * NOPE];    // k_nope (B,S,2048)
__device__ float g_v  [ROWS * HH * VHD];     // v  [b,s,h,128]
__device__ float g_K  [ROWS * HH * QKHD];    // assembled K [b,s,h,192] (reference reshape semantics)
__device__ float g_O  [ROWS * HH * VHD];     // attention out [b,s,h,128]

// ---------------- generic fp32 GEMM: C = A[MxK] * B[KxN] + bias ------------
__global__ void gemm_bias_kernel(const float* __restrict__ A,
                                 const float* __restrict__ B,
                                 const float* __restrict__ bias,
                                 float* __restrict__ C,
                                 int M, int N, int K)
{
    const int BM = 128, BN = 128, BK = 8;
    __shared__ float As[BK][BM];
    __shared__ float Bs[BK][BN];

    const int tid = threadIdx.x;
    const int tx = tid % 16;
    const int ty = tid / 16;
    const int row0 = blockIdx.y * BM;
    const int col0 = blockIdx.x * BN;

    const int ar = tid >> 1;            // 0..127
    const int ac = (tid & 1) * 4;       // 0 or 4
    const int br = tid >> 5;            // 0..7
    const int bc = (tid & 31) * 4;      // 0..124

    float acc[8][8];
    #pragma unroll
    for (int i = 0; i < 8; i++)
        #pragma unroll
        for (int j = 0; j < 8; j++) acc[i][j] = 0.f;

    for (int k0 = 0; k0 < K; k0 += BK) {
        float4 av = *(const float4*)&A[(size_t)(row0 + ar) * K + k0 + ac];
        As[ac + 0][ar] = av.x;
        As[ac + 1][ar] = av.y;
        As[ac + 2][ar] = av.z;
        As[ac + 3][ar] = av.w;
        float4 bv = *(const float4*)&B[(size_t)(k0 + br) * N + col0 + bc];
        *(float4*)&Bs[br][bc] = bv;
        __syncthreads();

        #pragma unroll
        for (int kk = 0; kk < BK; kk++) {
            float a[8], b[8];
            *(float4*)&a[0] = *(const float4*)&As[kk][ty * 8];
            *(float4*)&a[4] = *(const float4*)&As[kk][ty * 8 + 4];
            *(float4*)&b[0] = *(const float4*)&Bs[kk][tx * 8];
            *(float4*)&b[4] = *(const float4*)&Bs[kk][tx * 8 + 4];
            #pragma unroll
            for (int i = 0; i < 8; i++)
                #pragma unroll
                for (int j = 0; j < 8; j++)
                    acc[i][j] += a[i] * b[j];
        }
        __syncthreads();
    }

    #pragma unroll
    for (int i = 0; i < 8; i++) {
        int r = row0 + ty * 8 + i;
        #pragma unroll
        for (int j = 0; j < 8; j += 4) {
            int c = col0 + tx * 8 + j;
            float4 o;
            o.x = acc[i][j + 0] + bias[c + 0];
            o.y = acc[i][j + 1] + bias[c + 1];
            o.z = acc[i][j + 2] + bias[c + 2];
            o.w = acc[i][j + 3] + bias[c + 3];
            *(float4*)&C[(size_t)r * N + c] = o;
        }
    }
}

// ---------------- LayerNorm over the 512-wide latent slice ------------------
__global__ void ln_kernel(const float* __restrict__ kv,
                          const float* __restrict__ gamma,
                          const float* __restrict__ beta,
                          float* __restrict__ out)
{
    const int row = blockIdx.x;
    const float* src = kv + (size_t)row * KVCOLS + HH * ROPE;
    float* dst = out + (size_t)row * KVRANK;
    const int tid = threadIdx.x;   // 128 threads

    float v[4];
    float s = 0.f, s2 = 0.f;
    #pragma unroll
    for (int i = 0; i < 4; i++) {
        v[i] = src[tid + i * 128];
        s += v[i];
        s2 += v[i] * v[i];
    }
    __shared__ float rs[128], rs2[128];
    rs[tid] = s; rs2[tid] = s2;
    __syncthreads();
    for (int o = 64; o > 0; o >>= 1) {
        if (tid < o) { rs[tid] += rs[tid + o]; rs2[tid] += rs2[tid + o]; }
        __syncthreads();
    }
    float mean = rs[0] * (1.f / 512.f);
    float var  = rs2[0] * (1.f / 512.f) - mean * mean;
    float rstd = rsqrtf(var + 1e-5f);
    #pragma unroll
    for (int i = 0; i < 4; i++) {
        int c = tid + i * 128;
        dst[c] = (v[i] - mean) * rstd * gamma[c] + beta[c];
    }
}

// ---------------- RoPE + K assembly (REFERENCE reshape semantics) -----------
__global__ void rope_assemble_kernel(float* __restrict__ q,
                                     const float* __restrict__ kv,
                                     const float* __restrict__ knope,
                                     const float* __restrict__ cosT,
                                     const float* __restrict__ sinT,
                                     float* __restrict__ Kout)
{
    int idx = blockIdx.x * blockDim.x + threadIdx.x;
    if (idx >= ROWS * HH * 32) return;
    int p   = idx & 31;
    int h   = (idx >> 5) & 15;
    int row = idx >> 9;
    int s   = row & (SS - 1);

    float cv = cosT[s * 32 + p];
    float sv = sinT[s * 32 + p];

    // q rope (in place) — q is a direct reshape, per-head layout is natural
    size_t qb = (size_t)row * QCOLS + h * QKHD + NOPE + 2 * p;
    float a = q[qb], b = q[qb + 1];
    q[qb]     = a * cv - b * sv;
    q[qb + 1] = a * sv + b * cv;

    const float* knr = knope + (size_t)row * (HH * NOPE);   // 2048 values
    const float* krr = kv + (size_t)row * KVCOLS;            // first 1024 cols = k_rope
    size_t ko = ((size_t)row * HH + h) * QKHD;

    // nope part of head h: dims [0,128)
    {
        int g = h * QKHD + p * 4;        // multiple of 4
        float4 nv;
        if (g < HH * NOPE) nv = *(const float4*)&knr[g];
        else               nv = *(const float4*)&krr[g - HH * NOPE];
        *(float4*)&Kout[ko + p * 4] = nv;
    }

    // rope part of head h: dims d = 128+2p, 129+2p
    {
        int g = h * QKHD + NOPE + 2 * p;   // even; pair never straddles 2048
        float ka, kb;
        if (g < HH * NOPE) { ka = knr[g];             kb = knr[g + 1]; }
        else               { ka = krr[g - HH * NOPE]; kb = krr[g - HH * NOPE + 1]; }
        Kout[ko + NOPE + 2 * p]     = ka * cv - kb * sv;
        Kout[ko + NOPE + 2 * p + 1] = ka * sv + kb * cv;
    }
}

// ---------------- causal flash attention v2 (fp32, vectorized LDS) ----------
// BQ=64 q-rows, BKT=32 k-cols per tile, 256 threads.
// thread (tx=tid&7, ty=tid>>3): rows {ty, ty+32}, score cols tx*4..+3,
// PV cols {i*32 + tx*4 .. +3} for i in 0..3.
#define BQ   64
#define BKT  32
#define QP   196    // Q pad (mult of 4 -> LDS.128 aligned; rows hit distinct banks)
#define KP   36     // K^T pad (mult of 4; 8 float4/row cover all 32 banks)
#define VP   132    // V pad
#define PP   36     // P pad

__global__ __launch_bounds__(256, 2)
void attn_kernel(const float* __restrict__ Q,
                 const float* __restrict__ Kf,
                 const float* __restrict__ V,
                 float* __restrict__ O)
{
    const int q0 = blockIdx.x * BQ;
    const int h  = blockIdx.y;
    const int b  = blockIdx.z;

    extern __shared__ float sm[];
    float* Qs = sm;                    // [64][QP]
    float* Ks = Qs + BQ * QP;          // [192][KP]  (transposed)
    float* Vs = Ks + QKHD * KP;        // [32][VP]
    float* Ps = Vs + BKT * VP;         // [64][PP]

    const int tid = threadIdx.x;
    const int tx  = tid & 7;
    const int ty  = tid >> 3;
    const int r0  = ty;
    const int r1  = ty + 32;
    const float scale = 0.07216878364870322f;   // 192^-0.5

    // ---- load Q tile (float4, coalesced) ----
    const float* Qg = Q + (((size_t)(b * SS + q0)) * HH + h) * QKHD;
    #pragma unroll
    for (int n = 0; n < 12; n++) {          // 64*48 float4 / 256 threads
        int i = tid + n * 256;
        int r = i / 48, d4 = i % 48;
        float4 v = *(const float4*)&Qg[(size_t)r * (HH * QKHD) + d4 * 4];
        *(float4*)&Qs[r * QP + d4 * 4] = v;
    }

    float m0 = -INFINITY, l0 = 0.f, m1 = -INFINITY, l1 = 0.f;
    float acc0[16], acc1[16];
    #pragma unroll
    for (int i = 0; i < 16; i++) { acc0[i] = 0.f; acc1[i] = 0.f; }

    const int jend = (q0 + BQ - 1) / BKT;
    for (int j = 0; j <= jend; j++) {
        const int k0 = j * BKT;
        __syncthreads();    // prior tile fully consumed
        // ---- load K transposed ----
        const float* Kg = Kf + (((size_t)(b * SS + k0)) * HH + h) * QKHD;
        #pragma unroll
        for (int n = 0; n < 24; n++) {      // 32*192 / 256
            int i = tid + n * 256;
            int r = i / QKHD, d = i % QKHD;
            Ks[d * KP + r] = Kg[(size_t)r * (HH * QKHD) + d];
        }
        // ---- load V (float4) ----
        const float* Vg = V + (((size_t)(b * SS + k0)) * HH + h) * VHD;
        #pragma unroll
        for (int n = 0; n < 4; n++) {       // 32*32 float4 / 256
            int i = tid + n * 256;
            int r = i / 32, d4 = i % 32;
            *(float4*)&Vs[r * VP + d4 * 4] = *(const float4*)&Vg[(size_t)r * (HH * VHD) + d4 * 4];
        }
        __syncthreads();

        // ---- scores: 2 rows x 4 cols per thread ----
        float s0[4] = {0.f, 0.f, 0.f, 0.f};
        float s1[4] = {0.f, 0.f, 0.f, 0.f};
        const float* qr0 = &Qs[r0 * QP];
        const float* qr1 = &Qs[r1 * QP];
        #pragma unroll 2
        for (int d = 0; d < QKHD; d += 4) {
            float qa[4], qb[4];
            *(float4*)qa = *(const float4*)&qr0[d];
            *(float4*)qb = *(const float4*)&qr1[d];
            #pragma unroll
            for (int dd = 0; dd < 4; dd++) {
                float kv[4];
                *(float4*)kv = *(const float4*)&Ks[(d + dd) * KP + tx * 4];
                #pragma unroll
                for (int c = 0; c < 4; c++) {
                    s0[c] += qa[dd] * kv[c];
                    s1[c] += qb[dd] * kv[c];
                }
            }
        }

        // ---- scale + causal mask ----
        const int qi0 = q0 + r0, qi1 = q0 + r1;
        #pragma unroll
        for (int c = 0; c < 4; c++) {
            int kc = k0 + tx * 4 + c;
            s0[c] = (kc > qi0) ? -INFINITY : s0[c] * scale;
            s1[c] = (kc > qi1) ? -INFINITY : s1[c] * scale;
        }

        // ---- online softmax (reduce over 8 lanes sharing a row) ----
        float ml0 = fmaxf(fmaxf(s0[0], s0[1]), fmaxf(s0[2], s0[3]));
        float ml1 = fmaxf(fmaxf(s1[0], s1[1]), fmaxf(s1[2], s1[3]));
        #pragma unroll
        for (int o = 1; o < 8; o <<= 1) {
            ml0 = fmaxf(ml0, __shfl_xor_sync(0xffffffffu, ml0, o));
            ml1 = fmaxf(ml1, __shfl_xor_sync(0xffffffffu, ml1, o));
        }
        float mn0 = fmaxf(m0, ml0), mn1 = fmaxf(m1, ml1);
        // NaN-free reference point for fully-masked tiles
        float mr0 = (mn0 == -INFINITY) ? 0.f : mn0;
        float mr1 = (mn1 == -INFINITY) ? 0.f : mn1;

        float p0[4], p1[4], ll0 = 0.f, ll1 = 0.f;
        #pragma unroll
        for (int c = 0; c < 4; c++) {
            p0[c] = __expf(s0[c] - mr0);  ll0 += p0[c];
            p1[c] = __expf(s1[c] - mr1);  ll1 += p1[c];
        }
        #pragma unroll
        for (int o = 1; o < 8; o <<= 1) {
            ll0 += __shfl_xor_sync(0xffffffffu, ll0, o);
            ll1 += __shfl_xor_sync(0xffffffffu, ll1, o);
        }
        float a0 = __expf(m0 - mr0);   // m0=-inf -> 0 (mr finite): safe
        float a1 = __expf(m1 - mr1);
        m0 = mn0; m1 = mn1;
        l0 = l0 * a0 + ll0;
        l1 = l1 * a1 + ll1;

        *(float4*)&Ps[r0 * PP + tx * 4] = *(float4*)p0;
        *(float4*)&Ps[r1 * PP + tx * 4] = *(float4*)p1;
        #pragma unroll
        for (int i = 0; i < 16; i++) { acc0[i] *= a0; acc1[i] *= a1; }
        __syncthreads();

        // ---- PV: acc += P * V ----
        #pragma unroll 2
        for (int k = 0; k < BKT; k++) {
            float pv0 = Ps[r0 * PP + k];
            float pv1 = Ps[r1 * PP + k];
            const float* vrow = &Vs[k * VP];
            #pragma unroll
            for (int i = 0; i < 4; i++) {
                float v[4];
                *(float4*)v = *(const float4*)&vrow[i * 32 + tx * 4];
                #pragma unroll
                for (int c = 0; c < 4; c++) {
                    acc0[i * 4 + c] += pv0 * v[c];
                    acc1[i * 4 + c] += pv1 * v[c];
                }
            }
        }
    }

    // ---- write O ----
    float inv0 = 1.f / l0, inv1 = 1.f / l1;
    size_t ob0 = (((size_t)(b * SS + q0 + r0)) * HH + h) * VHD;
    size_t ob1 = (((size_t)(b * SS + q0 + r1)) * HH + h) * VHD;
    #pragma unroll
    for (int i = 0; i < 4; i++) {
        float4 o0, o1;
        o0.x = acc0[i*4+0]*inv0; o0.y = acc0[i*4+1]*inv0; o0.z = acc0[i*4+2]*inv0; o0.w = acc0[i*4+3]*inv0;
        o1.x = acc1[i*4+0]*inv1; o1.y = acc1[i*4+1]*inv1; o1.z = acc1[i*4+2]*inv1; o1.w = acc1[i*4+3]*inv1;
        *(float4*)&O[ob0 + i * 32 + tx * 4] = o0;
        *(float4*)&O[ob1 + i * 32 + tx * 4] = o1;
    }
}

#define ATTN_SMEM ((BQ*QP + QKHD*KP + BKT*VP + BQ*PP) * sizeof(float))

// ---------------- launch -----------------------------------------------------
extern "C" void kernel_launch(void* const* d_in, const int* in_sizes, int n_in,
                              void* d_out, int out_size)
{
    const float* x       = (const float*)d_in[0];
    const float* wq_w    = (const float*)d_in[1];
    const float* wq_b    = (const float*)d_in[2];
    const float* wkv_a_w = (const float*)d_in[3];
    const float* wkv_a_b = (const float*)d_in[4];
    const float* kvn_g   = (const float*)d_in[5];
    const float* kvn_b   = (const float*)d_in[6];
    const float* wk_w    = (const float*)d_in[7];
    const float* wk_b    = (const float*)d_in[8];
    const float* wv_w    = (const float*)d_in[9];
    const float* wv_b    = (const float*)d_in[10];
    const float* wo_w    = (const float*)d_in[11];
    const float* wo_b    = (const float*)d_in[12];
    const float* cosT    = (const float*)d_in[13];
    const float* sinT    = (const float*)d_in[14];
    float* out = (float*)d_out;

    float *gq, *gkv, *gc, *gkn, *gv, *gK, *gO;
    cudaGetSymbolAddress((void**)&gq,  g_q);
    cudaGetSymbolAddress((void**)&gkv, g_kv);
    cudaGetSymbolAddress((void**)&gc,  g_c);
    cudaGetSymbolAddress((void**)&gkn, g_kn);
    cudaGetSymbolAddress((void**)&gv,  g_v);
    cudaGetSymbolAddress((void**)&gK,  g_K);
    cudaGetSymbolAddress((void**)&gO,  g_O);

    // 1) q = x @ wq_w + b     [4096,3072] K=2048
    gemm_bias_kernel<<<dim3(QCOLS/128, ROWS/128), 256>>>(x, wq_w, wq_b, gq, ROWS, QCOLS, DIM);
    // 2) kv = x @ wkv_a_w + b [4096,1536] K=2048
    gemm_bias_kernel<<<dim3(KVCOLS/128, ROWS/128), 256>>>(x, wkv_a_w, wkv_a_b, gkv, ROWS, KVCOLS, DIM);
    // 3) layernorm latent
    ln_kernel<<<ROWS, 128>>>(gkv, kvn_g, kvn_b, gc);
    // 4) k_nope = c @ wk_w + b [4096,2048] K=512
    gemm_bias_kernel<<<dim3((HH*NOPE)/128, ROWS/128), 256>>>(gc, wk_w, wk_b, gkn, ROWS, HH*NOPE, KVRANK);
    // 5) v = c @ wv_w + b
    gemm_bias_kernel<<<dim3((HH*VHD)/128, ROWS/128), 256>>>(gc, wv_w, wv_b, gv, ROWS, HH*VHD, KVRANK);
    // 6) rope + assemble K (reference reshape semantics)
    {
        int total = ROWS * HH * 32;
        rope_assemble_kernel<<<(total + 255) / 256, 256>>>(gq, gkv, gkn, cosT, sinT, gK);
    }
    // 7) attention
    cudaFuncSetAttribute(attn_kernel, cudaFuncAttributeMaxDynamicSharedMemorySize, (int)ATTN_SMEM);
    attn_kernel<<<dim3(SS/BQ, HH, BB), 256, ATTN_SMEM>>>(gq, gK, gv, gO);
    // 8) out = O @ wo_w + b
    gemm_bias_kernel<<<dim3(DIM/128, ROWS/128), 256>>>(gO, wo_w, wo_b, out, ROWS, DIM, HH*VHD);
}

// round 4
// speedup vs baseline: 3.4362x; 1.8160x over previous
#include <cuda_runtime.h>
#include <cuda_bf16.h>
#include <math.h>
#include <stdint.h>

// ---------------- problem constants ----------------
#define BB    2
#define SS    2048
#define DIM   2048
#define HH    16
#define NOPE  128
#define ROPE  64
#define QKHD  192     // NOPE + ROPE
#define VHD   128
#define KVRANK 512
#define ROWS  (BB*SS)           // 4096
#define QCOLS (HH*QKHD)         // 3072
#define KVCOLS (KVRANK + HH*ROPE) // 1536

// ---------------- scratch (device globals; no allocation allowed) ----------
__device__ float g_q  [ROWS * QCOLS];
__device__ float g_kv [ROWS * KVCOLS];
__device__ float g_c  [ROWS * KVRANK];
__device__ float g_kn [ROWS * HH * NOPE];
__device__ float g_v  [ROWS * HH * VHD];
__device__ float g_K  [ROWS * HH * QKHD];
__device__ float g_O  [ROWS * HH * VHD];

// ---------------- tf32 tensor-core GEMM: C = A[MxK] @ B[KxN] + bias --------
// 128x128x32 tile, 256 threads (8 warps, 4x2), mma.sync.m16n8k8.tf32,
// cp.async double-buffered staging.
#define GBM 128
#define GBN 128
#define GBK 32
#define APAD 36     // As row stride (floats): banks 4g+tg conflict-free, 16B aligned
#define BPAD 136    // Bs row stride: banks 8tg+g conflict-free, 16B aligned
#define AS_STAGE (GBM*APAD)
#define BS_STAGE (GBK*BPAD)
#define GEMM_SMEM ((2*AS_STAGE + 2*BS_STAGE) * sizeof(float))

__device__ __forceinline__ uint32_t f2tf32(float f) {
    uint32_t r;
    asm("cvt.rna.tf32.f32 %0, %1;" : "=r"(r) : "f"(f));
    return r;
}

__device__ __forceinline__ void mma_tf32(float* d, const uint32_t* a, const uint32_t* b) {
    asm volatile(
        "mma.sync.aligned.m16n8k8.row.col.f32.tf32.tf32.f32 "
        "{%0,%1,%2,%3}, {%4,%5,%6,%7}, {%8,%9}, {%0,%1,%2,%3};"
        : "+f"(d[0]), "+f"(d[1]), "+f"(d[2]), "+f"(d[3])
        : "r"(a[0]), "r"(a[1]), "r"(a[2]), "r"(a[3]), "r"(b[0]), "r"(b[1]));
}

__global__ __launch_bounds__(256, 2)
void gemm_tf32_kernel(const float* __restrict__ A, const float* __restrict__ B,
                      const float* __restrict__ bias, float* __restrict__ C,
                      int M, int N, int K)
{
    extern __shared__ float sg[];
    float* As = sg;                    // [2][GBM][APAD]
    float* Bs = sg + 2 * AS_STAGE;     // [2][GBK][BPAD]

    const int tid  = threadIdx.x;
    const int lane = tid & 31;
    const int warp = tid >> 5;
    const int g  = lane >> 2;          // groupID (0..7)
    const int tg = lane & 3;           // thread in group (0..3)
    const int wm = warp & 3;           // warp row (0..3) -> 32 M-rows each
    const int wn = warp >> 2;          // warp col (0..1) -> 64 N-cols each
    const int row0 = blockIdx.y * GBM;
    const int col0 = blockIdx.x * GBN;

    const uint32_t as_base = (uint32_t)__cvta_generic_to_shared(As);
    const uint32_t bs_base = (uint32_t)__cvta_generic_to_shared(Bs);

    float acc[2][8][4];
    #pragma unroll
    for (int mt = 0; mt < 2; mt++)
        #pragma unroll
        for (int nt = 0; nt < 8; nt++)
            #pragma unroll
            for (int i = 0; i < 4; i++) acc[mt][nt][i] = 0.f;

#define STAGE_LOAD(s_, kt_) do {                                               \
    const float* Ag_ = A + (size_t)row0 * K + (size_t)(kt_) * GBK;             \
    _Pragma("unroll")                                                          \
    for (int n_ = 0; n_ < 4; n_++) {                                           \
        int i_ = tid + n_ * 256; int r_ = i_ >> 3; int c_ = (i_ & 7) * 4;      \
        uint32_t dst_ = as_base + (uint32_t)(((s_) * AS_STAGE + r_ * APAD + c_) * 4); \
        asm volatile("cp.async.cg.shared.global [%0], [%1], 16;"               \
                     :: "r"(dst_), "l"(Ag_ + (size_t)r_ * K + c_));            \
    }                                                                          \
    const float* Bg_ = B + (size_t)(kt_) * GBK * N + col0;                     \
    _Pragma("unroll")                                                          \
    for (int n_ = 0; n_ < 4; n_++) {                                           \
        int i_ = tid + n_ * 256; int r_ = i_ >> 5; int c_ = (i_ & 31) * 4;     \
        uint32_t dst_ = bs_base + (uint32_t)(((s_) * BS_STAGE + r_ * BPAD + c_) * 4); \
        asm volatile("cp.async.cg.shared.global [%0], [%1], 16;"               \
                     :: "r"(dst_), "l"(Bg_ + (size_t)r_ * N + c_));            \
    }                                                                          \
    asm volatile("cp.async.commit_group;");                                    \
} while (0)

    const int KT = K / GBK;
    STAGE_LOAD(0, 0);

    for (int kt = 0; kt < KT; kt++) {
        const int s = kt & 1;
        if (kt + 1 < KT) {
            STAGE_LOAD(1 - s, kt + 1);
            asm volatile("cp.async.wait_group 1;");
        } else {
            asm volatile("cp.async.wait_group 0;");
        }
        __syncthreads();

        const float* Asl = As + s * AS_STAGE;
        const float* Bsl = Bs + s * BS_STAGE;

        #pragma unroll
        for (int ks = 0; ks < 4; ks++) {
            uint32_t af[2][4], bf[8][2];
            const int kc = ks * 8 + tg;
            #pragma unroll
            for (int mt = 0; mt < 2; mt++) {
                int row = wm * 32 + mt * 16 + g;
                af[mt][0] = f2tf32(Asl[row * APAD + kc]);
                af[mt][1] = f2tf32(Asl[(row + 8) * APAD + kc]);
                af[mt][2] = f2tf32(Asl[row * APAD + kc + 4]);
                af[mt][3] = f2tf32(Asl[(row + 8) * APAD + kc + 4]);
            }
            #pragma unroll
            for (int nt = 0; nt < 8; nt++) {
                int col = wn * 64 + nt * 8 + g;
                bf[nt][0] = f2tf32(Bsl[kc * BPAD + col]);
                bf[nt][1] = f2tf32(Bsl[(kc + 4) * BPAD + col]);
            }
            #pragma unroll
            for (int mt = 0; mt < 2; mt++)
                #pragma unroll
                for (int nt = 0; nt < 8; nt++)
                    mma_tf32(acc[mt][nt], af[mt], bf[nt]);
        }
        __syncthreads();
    }
#undef STAGE_LOAD

    // epilogue: bias + store
    #pragma unroll
    for (int mt = 0; mt < 2; mt++) {
        int r = row0 + wm * 32 + mt * 16 + g;
        #pragma unroll
        for (int nt = 0; nt < 8; nt++) {
            int c = col0 + wn * 64 + nt * 8 + tg * 2;
            float b0 = bias[c], b1 = bias[c + 1];
            float2 v0 = make_float2(acc[mt][nt][0] + b0, acc[mt][nt][1] + b1);
            float2 v1 = make_float2(acc[mt][nt][2] + b0, acc[mt][nt][3] + b1);
            *(float2*)&C[(size_t)r * N + c]       = v0;
            *(float2*)&C[(size_t)(r + 8) * N + c] = v1;
        }
    }
}

// ---------------- LayerNorm over the 512-wide latent slice ------------------
__global__ void ln_kernel(const float* __restrict__ kv,
                          const float* __restrict__ gamma,
                          const float* __restrict__ beta,
                          float* __restrict__ out)
{
    const int row = blockIdx.x;
    const float* src = kv + (size_t)row * KVCOLS + HH * ROPE;
    float* dst = out + (size_t)row * KVRANK;
    const int tid = threadIdx.x;   // 128 threads

    float v[4];
    float s = 0.f, s2 = 0.f;
    #pragma unroll
    for (int i = 0; i < 4; i++) {
        v[i] = src[tid + i * 128];
        s += v[i];
        s2 += v[i] * v[i];
    }
    __shared__ float rs[128], rs2[128];
    rs[tid] = s; rs2[tid] = s2;
    __syncthreads();
    for (int o = 64; o > 0; o >>= 1) {
        if (tid < o) { rs[tid] += rs[tid + o]; rs2[tid] += rs2[tid + o]; }
        __syncthreads();
    }
    float mean = rs[0] * (1.f / 512.f);
    float var  = rs2[0] * (1.f / 512.f) - mean * mean;
    float rstd = rsqrtf(var + 1e-5f);
    #pragma unroll
    for (int i = 0; i < 4; i++) {
        int c = tid + i * 128;
        dst[c] = (v[i] - mean) * rstd * gamma[c] + beta[c];
    }
}

// ---------------- RoPE + K assembly (REFERENCE reshape semantics) -----------
__global__ void rope_assemble_kernel(float* __restrict__ q,
                                     const float* __restrict__ kv,
                                     const float* __restrict__ knope,
                                     const float* __restrict__ cosT,
                                     const float* __restrict__ sinT,
                                     float* __restrict__ Kout)
{
    int idx = blockIdx.x * blockDim.x + threadIdx.x;
    if (idx >= ROWS * HH * 32) return;
    int p   = idx & 31;
    int h   = (idx >> 5) & 15;
    int row = idx >> 9;
    int s   = row & (SS - 1);

    float cv = cosT[s * 32 + p];
    float sv = sinT[s * 32 + p];

    size_t qb = (size_t)row * QCOLS + h * QKHD + NOPE + 2 * p;
    float a = q[qb], b = q[qb + 1];
    q[qb]     = a * cv - b * sv;
    q[qb + 1] = a * sv + b * cv;

    const float* knr = knope + (size_t)row * (HH * NOPE);
    const float* krr = kv + (size_t)row * KVCOLS;
    size_t ko = ((size_t)row * HH + h) * QKHD;

    {
        int gg = h * QKHD + p * 4;
        float4 nv;
        if (gg < HH * NOPE) nv = *(const float4*)&knr[gg];
        else                nv = *(const float4*)&krr[gg - HH * NOPE];
        *(float4*)&Kout[ko + p * 4] = nv;
    }
    {
        int gg = h * QKHD + NOPE + 2 * p;
        float ka, kb;
        if (gg < HH * NOPE) { ka = knr[gg];              kb = knr[gg + 1]; }
        else                { ka = krr[gg - HH * NOPE];  kb = krr[gg - HH * NOPE + 1]; }
        Kout[ko + NOPE + 2 * p]     = ka * cv - kb * sv;
        Kout[ko + NOPE + 2 * p + 1] = ka * sv + kb * cv;
    }
}

// ---------------- causal flash attention (fp32, vectorized LDS) -------------
#define BQ   64
#define BKT  32
#define QP   196
#define KP   36
#define VP   132
#define PP   36

__global__ __launch_bounds__(256, 2)
void attn_kernel(const float* __restrict__ Q,
                 const float* __restrict__ Kf,
                 const float* __restrict__ V,
                 float* __restrict__ O)
{
    const int q0 = blockIdx.x * BQ;
    const int h  = blockIdx.y;
    const int b  = blockIdx.z;

    extern __shared__ float sm[];
    float* Qs = sm;
    float* Ks = Qs + BQ * QP;
    float* Vs = Ks + QKHD * KP;
    float* Ps = Vs + BKT * VP;

    const int tid = threadIdx.x;
    const int tx  = tid & 7;
    const int ty  = tid >> 3;
    const int r0  = ty;
    const int r1  = ty + 32;
    const float scale = 0.07216878364870322f;

    const float* Qg = Q + (((size_t)(b * SS + q0)) * HH + h) * QKHD;
    #pragma unroll
    for (int n = 0; n < 12; n++) {
        int i = tid + n * 256;
        int r = i / 48, d4 = i % 48;
        float4 v = *(const float4*)&Qg[(size_t)r * (HH * QKHD) + d4 * 4];
        *(float4*)&Qs[r * QP + d4 * 4] = v;
    }

    float m0 = -INFINITY, l0 = 0.f, m1 = -INFINITY, l1 = 0.f;
    float acc0[16], acc1[16];
    #pragma unroll
    for (int i = 0; i < 16; i++) { acc0[i] = 0.f; acc1[i] = 0.f; }

    const int jend = (q0 + BQ - 1) / BKT;
    for (int j = 0; j <= jend; j++) {
        const int k0 = j * BKT;
        __syncthreads();
        const float* Kg = Kf + (((size_t)(b * SS + k0)) * HH + h) * QKHD;
        #pragma unroll
        for (int n = 0; n < 24; n++) {
            int i = tid + n * 256;
            int r = i / QKHD, d = i % QKHD;
            Ks[d * KP + r] = Kg[(size_t)r * (HH * QKHD) + d];
        }
        const float* Vg = V + (((size_t)(b * SS + k0)) * HH + h) * VHD;
        #pragma unroll
        for (int n = 0; n < 4; n++) {
            int i = tid + n * 256;
            int r = i / 32, d4 = i % 32;
            *(float4*)&Vs[r * VP + d4 * 4] = *(const float4*)&Vg[(size_t)r * (HH * VHD) + d4 * 4];
        }
        __syncthreads();

        float s0[4] = {0.f, 0.f, 0.f, 0.f};
        float s1[4] = {0.f, 0.f, 0.f, 0.f};
        const float* qr0 = &Qs[r0 * QP];
        const float* qr1 = &Qs[r1 * QP];
        #pragma unroll 2
        for (int d = 0; d < QKHD; d += 4) {
            float qa[4], qb[4];
            *(float4*)qa = *(const float4*)&qr0[d];
            *(float4*)qb = *(const float4*)&qr1[d];
            #pragma unroll
            for (int dd = 0; dd < 4; dd++) {
                float kv[4];
                *(float4*)kv = *(const float4*)&Ks[(d + dd) * KP + tx * 4];
                #pragma unroll
                for (int c = 0; c < 4; c++) {
                    s0[c] += qa[dd] * kv[c];
                    s1[c] += qb[dd] * kv[c];
                }
            }
        }

        const int qi0 = q0 + r0, qi1 = q0 + r1;
        #pragma unroll
        for (int c = 0; c < 4; c++) {
            int kc = k0 + tx * 4 + c;
            s0[c] = (kc > qi0) ? -INFINITY : s0[c] * scale;
            s1[c] = (kc > qi1) ? -INFINITY : s1[c] * scale;
        }

        float ml0 = fmaxf(fmaxf(s0[0], s0[1]), fmaxf(s0[2], s0[3]));
        float ml1 = fmaxf(fmaxf(s1[0], s1[1]), fmaxf(s1[2], s1[3]));
        #pragma unroll
        for (int o = 1; o < 8; o <<= 1) {
            ml0 = fmaxf(ml0, __shfl_xor_sync(0xffffffffu, ml0, o));
            ml1 = fmaxf(ml1, __shfl_xor_sync(0xffffffffu, ml1, o));
        }
        float mn0 = fmaxf(m0, ml0), mn1 = fmaxf(m1, ml1);
        float mr0 = (mn0 == -INFINITY) ? 0.f : mn0;
        float mr1 = (mn1 == -INFINITY) ? 0.f : mn1;

        float p0[4], p1[4], ll0 = 0.f, ll1 = 0.f;
        #pragma unroll
        for (int c = 0; c < 4; c++) {
            p0[c] = __expf(s0[c] - mr0);  ll0 += p0[c];
            p1[c] = __expf(s1[c] - mr1);  ll1 += p1[c];
        }
        #pragma unroll
        for (int o = 1; o < 8; o <<= 1) {
            ll0 += __shfl_xor_sync(0xffffffffu, ll0, o);
            ll1 += __shfl_xor_sync(0xffffffffu, ll1, o);
        }
        float a0 = __expf(m0 - mr0);
        float a1 = __expf(m1 - mr1);
        m0 = mn0; m1 = mn1;
        l0 = l0 * a0 + ll0;
        l1 = l1 * a1 + ll1;

        *(float4*)&Ps[r0 * PP + tx * 4] = *(float4*)p0;
        *(float4*)&Ps[r1 * PP + tx * 4] = *(float4*)p1;
        #pragma unroll
        for (int i = 0; i < 16; i++) { acc0[i] *= a0; acc1[i] *= a1; }
        __syncthreads();

        #pragma unroll 2
        for (int k = 0; k < BKT; k++) {
            float pv0 = Ps[r0 * PP + k];
            float pv1 = Ps[r1 * PP + k];
            const float* vrow = &Vs[k * VP];
            #pragma unroll
            for (int i = 0; i < 4; i++) {
                float v[4];
                *(float4*)v = *(const float4*)&vrow[i * 32 + tx * 4];
                #pragma unroll
                for (int c = 0; c < 4; c++) {
                    acc0[i * 4 + c] += pv0 * v[c];
                    acc1[i * 4 + c] += pv1 * v[c];
                }
            }
        }
    }

    float inv0 = 1.f / l0, inv1 = 1.f / l1;
    size_t ob0 = (((size_t)(b * SS + q0 + r0)) * HH + h) * VHD;
    size_t ob1 = (((size_t)(b * SS + q0 + r1)) * HH + h) * VHD;
    #pragma unroll
    for (int i = 0; i < 4; i++) {
        float4 o0, o1;
        o0.x = acc0[i*4+0]*inv0; o0.y = acc0[i*4+1]*inv0; o0.z = acc0[i*4+2]*inv0; o0.w = acc0[i*4+3]*inv0;
        o1.x = acc1[i*4+0]*inv1; o1.y = acc1[i*4+1]*inv1; o1.z = acc1[i*4+2]*inv1; o1.w = acc1[i*4+3]*inv1;
        *(float4*)&O[ob0 + i * 32 + tx * 4] = o0;
        *(float4*)&O[ob1 + i * 32 + tx * 4] = o1;
    }
}

#define ATTN_SMEM ((BQ*QP + QKHD*KP + BKT*VP + BQ*PP) * sizeof(float))

// ---------------- launch -----------------------------------------------------
extern "C" void kernel_launch(void* const* d_in, const int* in_sizes, int n_in,
                              void* d_out, int out_size)
{
    const float* x       = (const float*)d_in[0];
    const float* wq_w    = (const float*)d_in[1];
    const float* wq_b    = (const float*)d_in[2];
    const float* wkv_a_w = (const float*)d_in[3];
    const float* wkv_a_b = (const float*)d_in[4];
    const float* kvn_g   = (const float*)d_in[5];
    const float* kvn_b   = (const float*)d_in[6];
    const float* wk_w    = (const float*)d_in[7];
    const float* wk_b    = (const float*)d_in[8];
    const float* wv_w    = (const float*)d_in[9];
    const float* wv_b    = (const float*)d_in[10];
    const float* wo_w    = (const float*)d_in[11];
    const float* wo_b    = (const float*)d_in[12];
    const float* cosT    = (const float*)d_in[13];
    const float* sinT    = (const float*)d_in[14];
    float* out = (float*)d_out;

    float *gq, *gkv, *gc, *gkn, *gv, *gK, *gO;
    cudaGetSymbolAddress((void**)&gq,  g_q);
    cudaGetSymbolAddress((void**)&gkv, g_kv);
    cudaGetSymbolAddress((void**)&gc,  g_c);
    cudaGetSymbolAddress((void**)&gkn, g_kn);
    cudaGetSymbolAddress((void**)&gv,  g_v);
    cudaGetSymbolAddress((void**)&gK,  g_K);
    cudaGetSymbolAddress((void**)&gO,  g_O);

    cudaFuncSetAttribute(gemm_tf32_kernel, cudaFuncAttributeMaxDynamicSharedMemorySize, (int)GEMM_SMEM);

    // 1) q = x @ wq_w + b     [4096,3072] K=2048
    gemm_tf32_kernel<<<dim3(QCOLS/GBN, ROWS/GBM), 256, GEMM_SMEM>>>(x, wq_w, wq_b, gq, ROWS, QCOLS, DIM);
    // 2) kv = x @ wkv_a_w + b [4096,1536] K=2048
    gemm_tf32_kernel<<<dim3(KVCOLS/GBN, ROWS/GBM), 256, GEMM_SMEM>>>(x, wkv_a_w, wkv_a_b, gkv, ROWS, KVCOLS, DIM);
    // 3) layernorm latent
    ln_kernel<<<ROWS, 128>>>(gkv, kvn_g, kvn_b, gc);
    // 4) k_nope = c @ wk_w + b [4096,2048] K=512
    gemm_tf32_kernel<<<dim3((HH*NOPE)/GBN, ROWS/GBM), 256, GEMM_SMEM>>>(gc, wk_w, wk_b, gkn, ROWS, HH*NOPE, KVRANK);
    // 5) v = c @ wv_w + b
    gemm_tf32_kernel<<<dim3((HH*VHD)/GBN, ROWS/GBM), 256, GEMM_SMEM>>>(gc, wv_w, wv_b, gv, ROWS, HH*VHD, KVRANK);
    // 6) rope + assemble K (reference reshape semantics)
    {
        int total = ROWS * HH * 32;
        rope_assemble_kernel<<<(total + 255) / 256, 256>>>(gq, gkv, gkn, cosT, sinT, gK);
    }
    // 7) attention
    cudaFuncSetAttribute(attn_kernel, cudaFuncAttributeMaxDynamicSharedMemorySize, (int)ATTN_SMEM);
    attn_kernel<<<dim3(SS/BQ, HH, BB), 256, ATTN_SMEM>>>(gq, gK, gv, gO);
    // 8) out = O @ wo_w + b
    gemm_tf32_kernel<<<dim3(DIM/GBN, ROWS/GBM), 256, GEMM_SMEM>>>(gO, wo_w, wo_b, out, ROWS, DIM, HH*VHD);
}

// round 5
// speedup vs baseline: 6.7663x; 1.9691x over previous
#include <cuda_runtime.h>
#include <cuda_bf16.h>
#include <math.h>
#include <stdint.h>

// ---------------- problem constants ----------------
#define BB    2
#define SS    2048
#define DIM   2048
#define HH    16
#define NOPE  128
#define ROPE  64
#define QKHD  192     // NOPE + ROPE
#define VHD   128
#define KVRANK 512
#define ROWS  (BB*SS)           // 4096
#define QCOLS (HH*QKHD)         // 3072
#define KVCOLS (KVRANK + HH*ROPE) // 1536

// ---------------- scratch (device globals; no allocation allowed) ----------
__device__ float g_q  [ROWS * QCOLS];
__device__ float g_kv [ROWS * KVCOLS];
__device__ float g_c  [ROWS * KVRANK];
__device__ float g_kn [ROWS * HH * NOPE];
__device__ float g_v  [ROWS * HH * VHD];
__device__ float g_K  [ROWS * HH * QKHD];
__device__ float g_O  [ROWS * HH * VHD];

// ---------------- tf32 helpers ----------------------------------------------
__device__ __forceinline__ uint32_t f2tf32(float f) {
    uint32_t r;
    asm("cvt.rna.tf32.f32 %0, %1;" : "=r"(r) : "f"(f));
    return r;
}
__device__ __forceinline__ float f2tf32f(float f) {
    return __uint_as_float(f2tf32(f));
}
__device__ __forceinline__ void mma_tf32(float* d, const uint32_t* a, const uint32_t* b) {
    asm volatile(
        "mma.sync.aligned.m16n8k8.row.col.f32.tf32.tf32.f32 "
        "{%0,%1,%2,%3}, {%4,%5,%6,%7}, {%8,%9}, {%0,%1,%2,%3};"
        : "+f"(d[0]), "+f"(d[1]), "+f"(d[2]), "+f"(d[3])
        : "r"(a[0]), "r"(a[1]), "r"(a[2]), "r"(a[3]), "r"(b[0]), "r"(b[1]));
}

// ---------------- tf32 tensor-core GEMM (validated in R4) -------------------
#define GBM 128
#define GBN 128
#define GBK 32
#define APAD 36
#define BPAD 136
#define AS_STAGE (GBM*APAD)
#define BS_STAGE (GBK*BPAD)
#define GEMM_SMEM ((2*AS_STAGE + 2*BS_STAGE) * sizeof(float))

__global__ __launch_bounds__(256, 2)
void gemm_tf32_kernel(const float* __restrict__ A, const float* __restrict__ B,
                      const float* __restrict__ bias, float* __restrict__ C,
                      int M, int N, int K)
{
    extern __shared__ float sg[];
    float* As = sg;
    float* Bs = sg + 2 * AS_STAGE;

    const int tid  = threadIdx.x;
    const int lane = tid & 31;
    const int warp = tid >> 5;
    const int g  = lane >> 2;
    const int tg = lane & 3;
    const int wm = warp & 3;
    const int wn = warp >> 2;
    const int row0 = blockIdx.y * GBM;
    const int col0 = blockIdx.x * GBN;

    const uint32_t as_base = (uint32_t)__cvta_generic_to_shared(As);
    const uint32_t bs_base = (uint32_t)__cvta_generic_to_shared(Bs);

    float acc[2][8][4];
    #pragma unroll
    for (int mt = 0; mt < 2; mt++)
        #pragma unroll
        for (int nt = 0; nt < 8; nt++)
            #pragma unroll
            for (int i = 0; i < 4; i++) acc[mt][nt][i] = 0.f;

#define STAGE_LOAD(s_, kt_) do {                                               \
    const float* Ag_ = A + (size_t)row0 * K + (size_t)(kt_) * GBK;             \
    _Pragma("unroll")                                                          \
    for (int n_ = 0; n_ < 4; n_++) {                                           \
        int i_ = tid + n_ * 256; int r_ = i_ >> 3; int c_ = (i_ & 7) * 4;      \
        uint32_t dst_ = as_base + (uint32_t)(((s_) * AS_STAGE + r_ * APAD + c_) * 4); \
        asm volatile("cp.async.cg.shared.global [%0], [%1], 16;"               \
                     :: "r"(dst_), "l"(Ag_ + (size_t)r_ * K + c_));            \
    }                                                                          \
    const float* Bg_ = B + (size_t)(kt_) * GBK * N + col0;                     \
    _Pragma("unroll")                                                          \
    for (int n_ = 0; n_ < 4; n_++) {                                           \
        int i_ = tid + n_ * 256; int r_ = i_ >> 5; int c_ = (i_ & 31) * 4;     \
        uint32_t dst_ = bs_base + (uint32_t)(((s_) * BS_STAGE + r_ * BPAD + c_) * 4); \
        asm volatile("cp.async.cg.shared.global [%0], [%1], 16;"               \
                     :: "r"(dst_), "l"(Bg_ + (size_t)r_ * N + c_));            \
    }                                                                          \
    asm volatile("cp.async.commit_group;");                                    \
} while (0)

    const int KT = K / GBK;
    STAGE_LOAD(0, 0);

    for (int kt = 0; kt < KT; kt++) {
        const int s = kt & 1;
        if (kt + 1 < KT) {
            STAGE_LOAD(1 - s, kt + 1);
            asm volatile("cp.async.wait_group 1;");
        } else {
            asm volatile("cp.async.wait_group 0;");
        }
        __syncthreads();

        const float* Asl = As + s * AS_STAGE;
        const float* Bsl = Bs + s * BS_STAGE;

        #pragma unroll
        for (int ks = 0; ks < 4; ks++) {
            uint32_t af[2][4], bf[8][2];
            const int kc = ks * 8 + tg;
            #pragma unroll
            for (int mt = 0; mt < 2; mt++) {
                int row = wm * 32 + mt * 16 + g;
                af[mt][0] = f2tf32(Asl[row * APAD + kc]);
                af[mt][1] = f2tf32(Asl[(row + 8) * APAD + kc]);
                af[mt][2] = f2tf32(Asl[row * APAD + kc + 4]);
                af[mt][3] = f2tf32(Asl[(row + 8) * APAD + kc + 4]);
            }
            #pragma unroll
            for (int nt = 0; nt < 8; nt++) {
                int col = wn * 64 + nt * 8 + g;
                bf[nt][0] = f2tf32(Bsl[kc * BPAD + col]);
                bf[nt][1] = f2tf32(Bsl[(kc + 4) * BPAD + col]);
            }
            #pragma unroll
            for (int mt = 0; mt < 2; mt++)
                #pragma unroll
                for (int nt = 0; nt < 8; nt++)
                    mma_tf32(acc[mt][nt], af[mt], bf[nt]);
        }
        __syncthreads();
    }
#undef STAGE_LOAD

    #pragma unroll
    for (int mt = 0; mt < 2; mt++) {
        int r = row0 + wm * 32 + mt * 16 + g;
        #pragma unroll
        for (int nt = 0; nt < 8; nt++) {
            int c = col0 + wn * 64 + nt * 8 + tg * 2;
            float b0 = bias[c], b1 = bias[c + 1];
            float2 v0 = make_float2(acc[mt][nt][0] + b0, acc[mt][nt][1] + b1);
            float2 v1 = make_float2(acc[mt][nt][2] + b0, acc[mt][nt][3] + b1);
            *(float2*)&C[(size_t)r * N + c]       = v0;
            *(float2*)&C[(size_t)(r + 8) * N + c] = v1;
        }
    }
}

// ---------------- LayerNorm over the 512-wide latent slice ------------------
__global__ void ln_kernel(const float* __restrict__ kv,
                          const float* __restrict__ gamma,
                          const float* __restrict__ beta,
                          float* __restrict__ out)
{
    const int row = blockIdx.x;
    const float* src = kv + (size_t)row * KVCOLS + HH * ROPE;
    float* dst = out + (size_t)row * KVRANK;
    const int tid = threadIdx.x;

    float v[4];
    float s = 0.f, s2 = 0.f;
    #pragma unroll
    for (int i = 0; i < 4; i++) {
        v[i] = src[tid + i * 128];
        s += v[i];
        s2 += v[i] * v[i];
    }
    __shared__ float rs[128], rs2[128];
    rs[tid] = s; rs2[tid] = s2;
    __syncthreads();
    for (int o = 64; o > 0; o >>= 1) {
        if (tid < o) { rs[tid] += rs[tid + o]; rs2[tid] += rs2[tid + o]; }
        __syncthreads();
    }
    float mean = rs[0] * (1.f / 512.f);
    float var  = rs2[0] * (1.f / 512.f) - mean * mean;
    float rstd = rsqrtf(var + 1e-5f);
    #pragma unroll
    for (int i = 0; i < 4; i++) {
        int c = tid + i * 128;
        dst[c] = (v[i] - mean) * rstd * gamma[c] + beta[c];
    }
}

// ---------------- RoPE + K assembly (REFERENCE reshape semantics) -----------
__global__ void rope_assemble_kernel(float* __restrict__ q,
                                     const float* __restrict__ kv,
                                     const float* __restrict__ knope,
                                     const float* __restrict__ cosT,
                                     const float* __restrict__ sinT,
                                     float* __restrict__ Kout)
{
    int idx = blockIdx.x * blockDim.x + threadIdx.x;
    if (idx >= ROWS * HH * 32) return;
    int p   = idx & 31;
    int h   = (idx >> 5) & 15;
    int row = idx >> 9;
    int s   = row & (SS - 1);

    float cv = cosT[s * 32 + p];
    float sv = sinT[s * 32 + p];

    size_t qb = (size_t)row * QCOLS + h * QKHD + NOPE + 2 * p;
    float a = q[qb], b = q[qb + 1];
    q[qb]     = a * cv - b * sv;
    q[qb + 1] = a * sv + b * cv;

    const float* knr = knope + (size_t)row * (HH * NOPE);
    const float* krr = kv + (size_t)row * KVCOLS;
    size_t ko = ((size_t)row * HH + h) * QKHD;

    {
        int gg = h * QKHD + p * 4;
        float4 nv;
        if (gg < HH * NOPE) nv = *(const float4*)&knr[gg];
        else                nv = *(const float4*)&krr[gg - HH * NOPE];
        *(float4*)&Kout[ko + p * 4] = nv;
    }
    {
        int gg = h * QKHD + NOPE + 2 * p;
        float ka, kb;
        if (gg < HH * NOPE) { ka = knr[gg];              kb = knr[gg + 1]; }
        else                { ka = krr[gg - HH * NOPE];  kb = krr[gg - HH * NOPE + 1]; }
        Kout[ko + NOPE + 2 * p]     = ka * cv - kb * sv;
        Kout[ko + NOPE + 2 * p + 1] = ka * sv + kb * cv;
    }
}

// ---------------- tf32 tensor-core causal flash attention -------------------
// BQ=64 q rows, BKT=64 kv per tile. 256 threads = 8 warps:
// warp = (wq in 0..3 -> 16 q rows, kh in 0..1 -> kv half of 32).
// Each warp: QK scores 16x32 (tf32 mma), warp-local online softmax,
// P -> smem -> PV mma 16x128. The two kv halves merge at the end.
#define ABQ 64
#define ABK 64
#define QSP 196
#define KSP 196
#define VSP 136
#define PSP 68
#define OSP 132
#define ATTN_SMEM ((ABQ*QSP + ABK*KSP + ABK*VSP + ABQ*PSP) * sizeof(float))

__global__ __launch_bounds__(256, 1)
void attn_mma_kernel(const float* __restrict__ Q,
                     const float* __restrict__ Kf,
                     const float* __restrict__ V,
                     float* __restrict__ O)
{
    const int q0 = blockIdx.x * ABQ;
    const int h  = blockIdx.y;
    const int b  = blockIdx.z;

    extern __shared__ float sm[];
    float* Qs = sm;                    // [64][QSP]
    float* Ks = Qs + ABQ * QSP;        // [64][KSP]
    float* Vs = Ks + ABK * KSP;        // [64][VSP]
    float* Ps = Vs + ABK * VSP;        // [64][PSP]

    const int tid  = threadIdx.x;
    const int lane = tid & 31;
    const int wid  = tid >> 5;
    const int g    = lane >> 2;
    const int tg   = lane & 3;
    const int wq   = wid & 3;          // q stripe
    const int kh   = wid >> 2;         // kv half
    const int rA   = wq * 16 + g;      // local q row (first of the lane's two)
    const float scale = 0.07216878364870322f;   // 192^-0.5

    // ---- load Q (pre-scaled, tf32-rounded) ----
    const float* Qg = Q + (((size_t)(b * SS + q0)) * HH + h) * QKHD;
    #pragma unroll
    for (int n = 0; n < 12; n++) {
        int i = tid + n * 256;
        int r = i / 48, d4 = (i % 48) * 4;
        float4 v = *(const float4*)&Qg[(size_t)r * (HH * QKHD) + d4];
        v.x = f2tf32f(v.x * scale); v.y = f2tf32f(v.y * scale);
        v.z = f2tf32f(v.z * scale); v.w = f2tf32f(v.w * scale);
        *(float4*)&Qs[r * QSP + d4] = v;
    }

    float m0 = -INFINITY, m1 = -INFINITY, l0 = 0.f, l1 = 0.f;
    float acc[16][4];
    #pragma unroll
    for (int nt = 0; nt < 16; nt++)
        #pragma unroll
        for (int i = 0; i < 4; i++) acc[nt][i] = 0.f;

    const int jend = blockIdx.x;       // q0 / ABK
    for (int j = 0; j <= jend; j++) {
        const int k0 = j * ABK;
        __syncthreads();
        // ---- stage K tile (tf32) ----
        const float* Kg = Kf + (((size_t)(b * SS + k0)) * HH + h) * QKHD;
        #pragma unroll
        for (int n = 0; n < 12; n++) {
            int i = tid + n * 256;
            int r = i / 48, d4 = (i % 48) * 4;
            float4 v = *(const float4*)&Kg[(size_t)r * (HH * QKHD) + d4];
            v.x = f2tf32f(v.x); v.y = f2tf32f(v.y);
            v.z = f2tf32f(v.z); v.w = f2tf32f(v.w);
            *(float4*)&Ks[r * KSP + d4] = v;
        }
        // ---- stage V tile (tf32) ----
        const float* Vg = V + (((size_t)(b * SS + k0)) * HH + h) * VHD;
        #pragma unroll
        for (int n = 0; n < 8; n++) {
            int i = tid + n * 256;
            int r = i / 32, d4 = (i % 32) * 4;
            float4 v = *(const float4*)&Vg[(size_t)r * (HH * VHD) + d4];
            v.x = f2tf32f(v.x); v.y = f2tf32f(v.y);
            v.z = f2tf32f(v.z); v.w = f2tf32f(v.w);
            *(float4*)&Vs[r * VSP + d4] = v;
        }
        __syncthreads();

        // ---- QK^T scores: 16x32 per warp ----
        float sc[4][4];
        #pragma unroll
        for (int nt = 0; nt < 4; nt++)
            #pragma unroll
            for (int i = 0; i < 4; i++) sc[nt][i] = 0.f;

        #pragma unroll
        for (int kc = 0; kc < 24; kc++) {
            uint32_t af[4];
            af[0] = __float_as_uint(Qs[rA * QSP + kc * 8 + tg]);
            af[1] = __float_as_uint(Qs[(rA + 8) * QSP + kc * 8 + tg]);
            af[2] = __float_as_uint(Qs[rA * QSP + kc * 8 + tg + 4]);
            af[3] = __float_as_uint(Qs[(rA + 8) * QSP + kc * 8 + tg + 4]);
            #pragma unroll
            for (int nt = 0; nt < 4; nt++) {
                int kvr = kh * 32 + nt * 8 + g;
                uint32_t bf[2];
                bf[0] = __float_as_uint(Ks[kvr * KSP + kc * 8 + tg]);
                bf[1] = __float_as_uint(Ks[kvr * KSP + kc * 8 + tg + 4]);
                mma_tf32(sc[nt], af, bf);
            }
        }

        // ---- causal mask (diagonal tile only) ----
        if (j == jend) {
            #pragma unroll
            for (int nt = 0; nt < 4; nt++) {
                int colb = k0 + kh * 32 + nt * 8 + 2 * tg;
                int row0g = q0 + rA, row1g = q0 + rA + 8;
                if (colb     > row0g) sc[nt][0] = -INFINITY;
                if (colb + 1 > row0g) sc[nt][1] = -INFINITY;
                if (colb     > row1g) sc[nt][2] = -INFINITY;
                if (colb + 1 > row1g) sc[nt][3] = -INFINITY;
            }
        }

        // ---- online softmax (rows warp-local: reduce over tg quad) ----
        float ml0 = -INFINITY, ml1 = -INFINITY;
        #pragma unroll
        for (int nt = 0; nt < 4; nt++) {
            ml0 = fmaxf(ml0, fmaxf(sc[nt][0], sc[nt][1]));
            ml1 = fmaxf(ml1, fmaxf(sc[nt][2], sc[nt][3]));
        }
        ml0 = fmaxf(ml0, __shfl_xor_sync(0xffffffffu, ml0, 1));
        ml0 = fmaxf(ml0, __shfl_xor_sync(0xffffffffu, ml0, 2));
        ml1 = fmaxf(ml1, __shfl_xor_sync(0xffffffffu, ml1, 1));
        ml1 = fmaxf(ml1, __shfl_xor_sync(0xffffffffu, ml1, 2));
        float mn0 = fmaxf(m0, ml0), mn1 = fmaxf(m1, ml1);
        float mr0 = (mn0 == -INFINITY) ? 0.f : mn0;
        float mr1 = (mn1 == -INFINITY) ? 0.f : mn1;
        float a0 = __expf(m0 - mr0);
        float a1 = __expf(m1 - mr1);

        float ll0 = 0.f, ll1 = 0.f;
        #pragma unroll
        for (int nt = 0; nt < 4; nt++) {
            float p0 = __expf(sc[nt][0] - mr0);
            float p1 = __expf(sc[nt][1] - mr0);
            float p2 = __expf(sc[nt][2] - mr1);
            float p3 = __expf(sc[nt][3] - mr1);
            ll0 += p0 + p1;
            ll1 += p2 + p3;
            int cb = kh * 32 + nt * 8 + 2 * tg;
            *(float2*)&Ps[rA * PSP + cb]       = make_float2(f2tf32f(p0), f2tf32f(p1));
            *(float2*)&Ps[(rA + 8) * PSP + cb] = make_float2(f2tf32f(p2), f2tf32f(p3));
        }
        ll0 += __shfl_xor_sync(0xffffffffu, ll0, 1);
        ll0 += __shfl_xor_sync(0xffffffffu, ll0, 2);
        ll1 += __shfl_xor_sync(0xffffffffu, ll1, 1);
        ll1 += __shfl_xor_sync(0xffffffffu, ll1, 2);

        m0 = mn0; m1 = mn1;
        l0 = l0 * a0 + ll0;
        l1 = l1 * a1 + ll1;

        #pragma unroll
        for (int nt = 0; nt < 16; nt++) {
            acc[nt][0] *= a0; acc[nt][1] *= a0;
            acc[nt][2] *= a1; acc[nt][3] *= a1;
        }
        __syncwarp();

        // ---- PV: 16x128 per warp over its 32-kv half ----
        #pragma unroll
        for (int kc = 0; kc < 4; kc++) {
            uint32_t af[4];
            int pc = kh * 32 + kc * 8;
            af[0] = __float_as_uint(Ps[rA * PSP + pc + tg]);
            af[1] = __float_as_uint(Ps[(rA + 8) * PSP + pc + tg]);
            af[2] = __float_as_uint(Ps[rA * PSP + pc + tg + 4]);
            af[3] = __float_as_uint(Ps[(rA + 8) * PSP + pc + tg + 4]);
            int kv0 = kh * 32 + kc * 8 + tg;
            #pragma unroll
            for (int nt = 0; nt < 16; nt++) {
                uint32_t bf[2];
                bf[0] = __float_as_uint(Vs[kv0 * VSP + nt * 8 + g]);
                bf[1] = __float_as_uint(Vs[(kv0 + 4) * VSP + nt * 8 + g]);
                mma_tf32(acc[nt], af, bf);
            }
        }
        __syncwarp();
    }

    // ---- merge the two kv halves (group B -> smem, group A combines) ----
    __syncthreads();
    float* Osh = Ks;            // reuse: [64][OSP]
    float* msh = Ps;            // [64] row max (group B)
    float* lsh = Ps + 64;       // [64] row sum (group B)

    if (kh == 1) {
        if (tg == 0) {
            msh[rA] = m0;  msh[rA + 8] = m1;
            lsh[rA] = l0;  lsh[rA + 8] = l1;
        }
        #pragma unroll
        for (int nt = 0; nt < 16; nt++) {
            int cb = nt * 8 + 2 * tg;
            *(float2*)&Osh[rA * OSP + cb]       = make_float2(acc[nt][0], acc[nt][1]);
            *(float2*)&Osh[(rA + 8) * OSP + cb] = make_float2(acc[nt][2], acc[nt][3]);
        }
    }
    __syncthreads();
    if (kh == 0) {
        float mB0 = msh[rA], mB1 = msh[rA + 8];
        float lB0 = lsh[rA], lB1 = lsh[rA + 8];
        float mm0 = fmaxf(m0, mB0), mm1 = fmaxf(m1, mB1);
        float wA0 = __expf(m0 - mm0),  wB0 = __expf(mB0 - mm0);
        float wA1 = __expf(m1 - mm1),  wB1 = __expf(mB1 - mm1);
        float inv0 = 1.f / (wA0 * l0 + wB0 * lB0);
        float inv1 = 1.f / (wA1 * l1 + wB1 * lB1);

        size_t ob0 = (((size_t)(b * SS + q0 + rA)) * HH + h) * VHD;
        size_t ob1 = (((size_t)(b * SS + q0 + rA + 8)) * HH + h) * VHD;
        #pragma unroll
        for (int nt = 0; nt < 16; nt++) {
            int cb = nt * 8 + 2 * tg;
            float2 oB0 = *(float2*)&Osh[rA * OSP + cb];
            float2 oB1 = *(float2*)&Osh[(rA + 8) * OSP + cb];
            float2 r0, r1;
            r0.x = (wA0 * acc[nt][0] + wB0 * oB0.x) * inv0;
            r0.y = (wA0 * acc[nt][1] + wB0 * oB0.y) * inv0;
            r1.x = (wA1 * acc[nt][2] + wB1 * oB1.x) * inv1;
            r1.y = (wA1 * acc[nt][3] + wB1 * oB1.y) * inv1;
            *(float2*)&O[ob0 + cb] = r0;
            *(float2*)&O[ob1 + cb] = r1;
        }
    }
}

// ---------------- launch -----------------------------------------------------
extern "C" void kernel_launch(void* const* d_in, const int* in_sizes, int n_in,
                              void* d_out, int out_size)
{
    const float* x       = (const float*)d_in[0];
    const float* wq_w    = (const float*)d_in[1];
    const float* wq_b    = (const float*)d_in[2];
    const float* wkv_a_w = (const float*)d_in[3];
    const float* wkv_a_b = (const float*)d_in[4];
    const float* kvn_g   = (const float*)d_in[5];
    const float* kvn_b   = (const float*)d_in[6];
    const float* wk_w    = (const float*)d_in[7];
    const float* wk_b    = (const float*)d_in[8];
    const float* wv_w    = (const float*)d_in[9];
    const float* wv_b    = (const float*)d_in[10];
    const float* wo_w    = (const float*)d_in[11];
    const float* wo_b    = (const float*)d_in[12];
    const float* cosT    = (const float*)d_in[13];
    const float* sinT    = (const float*)d_in[14];
    float* out = (float*)d_out;

    float *gq, *gkv, *gc, *gkn, *gv, *gK, *gO;
    cudaGetSymbolAddress((void**)&gq,  g_q);
    cudaGetSymbolAddress((void**)&gkv, g_kv);
    cudaGetSymbolAddress((void**)&gc,  g_c);
    cudaGetSymbolAddress((void**)&gkn, g_kn);
    cudaGetSymbolAddress((void**)&gv,  g_v);
    cudaGetSymbolAddress((void**)&gK,  g_K);
    cudaGetSymbolAddress((void**)&gO,  g_O);

    cudaFuncSetAttribute(gemm_tf32_kernel, cudaFuncAttributeMaxDynamicSharedMemorySize, (int)GEMM_SMEM);
    cudaFuncSetAttribute(attn_mma_kernel, cudaFuncAttributeMaxDynamicSharedMemorySize, (int)ATTN_SMEM);

    // 1) q = x @ wq_w + b
    gemm_tf32_kernel<<<dim3(QCOLS/GBN, ROWS/GBM), 256, GEMM_SMEM>>>(x, wq_w, wq_b, gq, ROWS, QCOLS, DIM);
    // 2) kv = x @ wkv_a_w + b
    gemm_tf32_kernel<<<dim3(KVCOLS/GBN, ROWS/GBM), 256, GEMM_SMEM>>>(x, wkv_a_w, wkv_a_b, gkv, ROWS, KVCOLS, DIM);
    // 3) layernorm latent
    ln_kernel<<<ROWS, 128>>>(gkv, kvn_g, kvn_b, gc);
    // 4) k_nope = c @ wk_w + b
    gemm_tf32_kernel<<<dim3((HH*NOPE)/GBN, ROWS/GBM), 256, GEMM_SMEM>>>(gc, wk_w, wk_b, gkn, ROWS, HH*NOPE, KVRANK);
    // 5) v = c @ wv_w + b
    gemm_tf32_kernel<<<dim3((HH*VHD)/GBN, ROWS/GBM), 256, GEMM_SMEM>>>(gc, wv_w, wv_b, gv, ROWS, HH*VHD, KVRANK);
    // 6) rope + assemble K
    {
        int total = ROWS * HH * 32;
        rope_assemble_kernel<<<(total + 255) / 256, 256>>>(gq, gkv, gkn, cosT, sinT, gK);
    }
    // 7) attention (tf32 tensor cores)
    attn_mma_kernel<<<dim3(SS/ABQ, HH, BB), 256, ATTN_SMEM>>>(gq, gK, gv, gO);
    // 8) out = O @ wo_w + b
    gemm_tf32_kernel<<<dim3(DIM/GBN, ROWS/GBM), 256, GEMM_SMEM>>>(gO, wo_w, wo_b, out, ROWS, DIM, HH*VHD);
}

// round 6
// speedup vs baseline: 6.9364x; 1.0251x over previous
#include <cuda_runtime.h>
#include <cuda_bf16.h>
#include <math.h>
#include <stdint.h>

// ---------------- problem constants ----------------
#define BB    2
#define SS    2048
#define DIM   2048
#define HH    16
#define NOPE  128
#define ROPE  64
#define QKHD  192     // NOPE + ROPE
#define VHD   128
#define KVRANK 512
#define ROWS  (BB*SS)           // 4096
#define QCOLS (HH*QKHD)         // 3072
#define KVCOLS (KVRANK + HH*ROPE) // 1536

// ---------------- scratch (device globals; no allocation allowed) ----------
__device__ float g_q  [ROWS * QCOLS];
__device__ float g_kv [ROWS * KVCOLS];
__device__ float g_c  [ROWS * KVRANK];        // tf32-rounded latent (GEMM input)
__device__ float g_kn [ROWS * HH * NOPE];
__device__ float g_v  [ROWS * HH * VHD];
__device__ float g_K  [ROWS * HH * QKHD];
__device__ float g_O  [ROWS * HH * VHD];      // tf32-rounded attention out (GEMM input)
// tf32-rounded operand copies
__device__ float g_xt   [ROWS * DIM];
__device__ float g_wqt  [DIM * QCOLS];
__device__ float g_wkvt [DIM * KVCOLS];
__device__ float g_wkt  [KVRANK * HH * NOPE];
__device__ float g_wvt  [KVRANK * HH * VHD];
__device__ float g_wot  [HH * VHD * DIM];

// ---------------- tf32 helpers ----------------------------------------------
__device__ __forceinline__ uint32_t f2tf32(float f) {
    uint32_t r;
    asm("cvt.rna.tf32.f32 %0, %1;" : "=r"(r) : "f"(f));
    return r;
}
__device__ __forceinline__ float f2tf32f(float f) {
    return __uint_as_float(f2tf32(f));
}
__device__ __forceinline__ void mma_tf32(float* d, const uint32_t* a, const uint32_t* b) {
    asm volatile(
        "mma.sync.aligned.m16n8k8.row.col.f32.tf32.tf32.f32 "
        "{%0,%1,%2,%3}, {%4,%5,%6,%7}, {%8,%9}, {%0,%1,%2,%3};"
        : "+f"(d[0]), "+f"(d[1]), "+f"(d[2]), "+f"(d[3])
        : "r"(a[0]), "r"(a[1]), "r"(a[2]), "r"(a[3]), "r"(b[0]), "r"(b[1]));
}

// ---------------- elementwise tf32 rounding pass -----------------------------
__global__ void tf32_convert_kernel(const float* __restrict__ src,
                                    float* __restrict__ dst, int n4)
{
    int i = blockIdx.x * blockDim.x + threadIdx.x;
    if (i >= n4) return;
    float4 v = *(const float4*)&src[i * 4];
    v.x = f2tf32f(v.x); v.y = f2tf32f(v.y);
    v.z = f2tf32f(v.z); v.w = f2tf32f(v.w);
    *(float4*)&dst[i * 4] = v;
}

// ---------------- tf32 tensor-core GEMM (operands pre-rounded) --------------
#define GBM 128
#define GBN 128
#define GBK 32
#define APAD 36
#define BPAD 136
#define AS_STAGE (GBM*APAD)
#define BS_STAGE (GBK*BPAD)
#define GEMM_SMEM ((2*AS_STAGE + 2*BS_STAGE) * sizeof(float))

__global__ __launch_bounds__(256, 2)
void gemm_tf32_kernel(const float* __restrict__ A, const float* __restrict__ B,
                      const float* __restrict__ bias, float* __restrict__ C,
                      int M, int N, int K)
{
    extern __shared__ float sg[];
    float* As = sg;
    float* Bs = sg + 2 * AS_STAGE;
    const uint32_t* Asu = (const uint32_t*)As;
    const uint32_t* Bsu = (const uint32_t*)Bs;

    const int tid  = threadIdx.x;
    const int lane = tid & 31;
    const int warp = tid >> 5;
    const int g  = lane >> 2;
    const int tg = lane & 3;
    const int wm = warp & 3;
    const int wn = warp >> 2;
    const int row0 = blockIdx.y * GBM;
    const int col0 = blockIdx.x * GBN;

    const uint32_t as_base = (uint32_t)__cvta_generic_to_shared(As);
    const uint32_t bs_base = (uint32_t)__cvta_generic_to_shared(Bs);

    float acc[2][8][4];
    #pragma unroll
    for (int mt = 0; mt < 2; mt++)
        #pragma unroll
        for (int nt = 0; nt < 8; nt++)
            #pragma unroll
            for (int i = 0; i < 4; i++) acc[mt][nt][i] = 0.f;

#define STAGE_LOAD(s_, kt_) do {                                               \
    const float* Ag_ = A + (size_t)row0 * K + (size_t)(kt_) * GBK;             \
    _Pragma("unroll")                                                          \
    for (int n_ = 0; n_ < 4; n_++) {                                           \
        int i_ = tid + n_ * 256; int r_ = i_ >> 3; int c_ = (i_ & 7) * 4;      \
        uint32_t dst_ = as_base + (uint32_t)(((s_) * AS_STAGE + r_ * APAD + c_) * 4); \
        asm volatile("cp.async.cg.shared.global [%0], [%1], 16;"               \
                     :: "r"(dst_), "l"(Ag_ + (size_t)r_ * K + c_));            \
    }                                                                          \
    const float* Bg_ = B + (size_t)(kt_) * GBK * N + col0;                     \
    _Pragma("unroll")                                                          \
    for (int n_ = 0; n_ < 4; n_++) {                                           \
        int i_ = tid + n_ * 256; int r_ = i_ >> 5; int c_ = (i_ & 31) * 4;     \
        uint32_t dst_ = bs_base + (uint32_t)(((s_) * BS_STAGE + r_ * BPAD + c_) * 4); \
        asm volatile("cp.async.cg.shared.global [%0], [%1], 16;"               \
                     :: "r"(dst_), "l"(Bg_ + (size_t)r_ * N + c_));            \
    }                                                                          \
    asm volatile("cp.async.commit_group;");                                    \
} while (0)

    const int KT = K / GBK;
    STAGE_LOAD(0, 0);

    for (int kt = 0; kt < KT; kt++) {
        const int s = kt & 1;
        if (kt + 1 < KT) {
            STAGE_LOAD(1 - s, kt + 1);
            asm volatile("cp.async.wait_group 1;");
        } else {
            asm volatile("cp.async.wait_group 0;");
        }
        __syncthreads();

        const uint32_t* Asl = Asu + s * AS_STAGE;
        const uint32_t* Bsl = Bsu + s * BS_STAGE;

        #pragma unroll
        for (int ks = 0; ks < 4; ks++) {
            uint32_t af[2][4], bf[8][2];
            const int kc = ks * 8 + tg;
            #pragma unroll
            for (int mt = 0; mt < 2; mt++) {
                int row = wm * 32 + mt * 16 + g;
                af[mt][0] = Asl[row * APAD + kc];
                af[mt][1] = Asl[(row + 8) * APAD + kc];
                af[mt][2] = Asl[row * APAD + kc + 4];
                af[mt][3] = Asl[(row + 8) * APAD + kc + 4];
            }
            #pragma unroll
            for (int nt = 0; nt < 8; nt++) {
                int col = wn * 64 + nt * 8 + g;
                bf[nt][0] = Bsl[kc * BPAD + col];
                bf[nt][1] = Bsl[(kc + 4) * BPAD + col];
            }
            #pragma unroll
            for (int mt = 0; mt < 2; mt++)
                #pragma unroll
                for (int nt = 0; nt < 8; nt++)
                    mma_tf32(acc[mt][nt], af[mt], bf[nt]);
        }
        __syncthreads();
    }
#undef STAGE_LOAD

    #pragma unroll
    for (int mt = 0; mt < 2; mt++) {
        int r = row0 + wm * 32 + mt * 16 + g;
        #pragma unroll
        for (int nt = 0; nt < 8; nt++) {
            int c = col0 + wn * 64 + nt * 8 + tg * 2;
            float b0 = bias[c], b1 = bias[c + 1];
            float2 v0 = make_float2(acc[mt][nt][0] + b0, acc[mt][nt][1] + b1);
            float2 v1 = make_float2(acc[mt][nt][2] + b0, acc[mt][nt][3] + b1);
            *(float2*)&C[(size_t)r * N + c]       = v0;
            *(float2*)&C[(size_t)(r + 8) * N + c] = v1;
        }
    }
}

// ---------------- LayerNorm (emits tf32-rounded output) ---------------------
__global__ void ln_kernel(const float* __restrict__ kv,
                          const float* __restrict__ gamma,
                          const float* __restrict__ beta,
                          float* __restrict__ out)
{
    const int row = blockIdx.x;
    const float* src = kv + (size_t)row * KVCOLS + HH * ROPE;
    float* dst = out + (size_t)row * KVRANK;
    const int tid = threadIdx.x;

    float v[4];
    float s = 0.f, s2 = 0.f;
    #pragma unroll
    for (int i = 0; i < 4; i++) {
        v[i] = src[tid + i * 128];
        s += v[i];
        s2 += v[i] * v[i];
    }
    __shared__ float rs[128], rs2[128];
    rs[tid] = s; rs2[tid] = s2;
    __syncthreads();
    for (int o = 64; o > 0; o >>= 1) {
        if (tid < o) { rs[tid] += rs[tid + o]; rs2[tid] += rs2[tid + o]; }
        __syncthreads();
    }
    float mean = rs[0] * (1.f / 512.f);
    float var  = rs2[0] * (1.f / 512.f) - mean * mean;
    float rstd = rsqrtf(var + 1e-5f);
    #pragma unroll
    for (int i = 0; i < 4; i++) {
        int c = tid + i * 128;
        dst[c] = f2tf32f((v[i] - mean) * rstd * gamma[c] + beta[c]);
    }
}

// ---------------- RoPE + K assembly (REFERENCE reshape semantics) -----------
__global__ void rope_assemble_kernel(float* __restrict__ q,
                                     const float* __restrict__ kv,
                                     const float* __restrict__ knope,
                                     const float* __restrict__ cosT,
                                     const float* __restrict__ sinT,
                                     float* __restrict__ Kout)
{
    int idx = blockIdx.x * blockDim.x + threadIdx.x;
    if (idx >= ROWS * HH * 32) return;
    int p   = idx & 31;
    int h   = (idx >> 5) & 15;
    int row = idx >> 9;
    int s   = row & (SS - 1);

    float cv = cosT[s * 32 + p];
    float sv = sinT[s * 32 + p];

    size_t qb = (size_t)row * QCOLS + h * QKHD + NOPE + 2 * p;
    float a = q[qb], b = q[qb + 1];
    q[qb]     = a * cv - b * sv;
    q[qb + 1] = a * sv + b * cv;

    const float* knr = knope + (size_t)row * (HH * NOPE);
    const float* krr = kv + (size_t)row * KVCOLS;
    size_t ko = ((size_t)row * HH + h) * QKHD;

    {
        int gg = h * QKHD + p * 4;
        float4 nv;
        if (gg < HH * NOPE) nv = *(const float4*)&knr[gg];
        else                nv = *(const float4*)&krr[gg - HH * NOPE];
        *(float4*)&Kout[ko + p * 4] = nv;
    }
    {
        int gg = h * QKHD + NOPE + 2 * p;
        float ka, kb;
        if (gg < HH * NOPE) { ka = knr[gg];              kb = knr[gg + 1]; }
        else                { ka = krr[gg - HH * NOPE];  kb = krr[gg - HH * NOPE + 1]; }
        Kout[ko + NOPE + 2 * p]     = ka * cv - kb * sv;
        Kout[ko + NOPE + 2 * p + 1] = ka * sv + kb * cv;
    }
}

// ---------------- tf32 tensor-core causal flash attention -------------------
#define ABQ 64
#define ABK 64
#define QSP 196
#define KSP 196
#define VSP 136
#define PSP 68
#define OSP 132
#define ATTN_SMEM ((ABQ*QSP + ABK*KSP + ABK*VSP + ABQ*PSP) * sizeof(float))

__global__ __launch_bounds__(256, 1)
void attn_mma_kernel(const float* __restrict__ Q,
                     const float* __restrict__ Kf,
                     const float* __restrict__ V,
                     float* __restrict__ O)
{
    const int q0 = blockIdx.x * ABQ;
    const int h  = blockIdx.y;
    const int b  = blockIdx.z;

    extern __shared__ float sm[];
    float* Qs = sm;
    float* Ks = Qs + ABQ * QSP;
    float* Vs = Ks + ABK * KSP;
    float* Ps = Vs + ABK * VSP;

    const int tid  = threadIdx.x;
    const int lane = tid & 31;
    const int wid  = tid >> 5;
    const int g    = lane >> 2;
    const int tg   = lane & 3;
    const int wq   = wid & 3;
    const int kh   = wid >> 2;
    const int rA   = wq * 16 + g;
    const float scale = 0.07216878364870322f;

    const float* Qg = Q + (((size_t)(b * SS + q0)) * HH + h) * QKHD;
    #pragma unroll
    for (int n = 0; n < 12; n++) {
        int i = tid + n * 256;
        int r = i / 48, d4 = (i % 48) * 4;
        float4 v = *(const float4*)&Qg[(size_t)r * (HH * QKHD) + d4];
        v.x = f2tf32f(v.x * scale); v.y = f2tf32f(v.y * scale);
        v.z = f2tf32f(v.z * scale); v.w = f2tf32f(v.w * scale);
        *(float4*)&Qs[r * QSP + d4] = v;
    }

    float m0 = -INFINITY, m1 = -INFINITY, l0 = 0.f, l1 = 0.f;
    float acc[16][4];
    #pragma unroll
    for (int nt = 0; nt < 16; nt++)
        #pragma unroll
        for (int i = 0; i < 4; i++) acc[nt][i] = 0.f;

    const int jend = blockIdx.x;
    for (int j = 0; j <= jend; j++) {
        const int k0 = j * ABK;
        __syncthreads();
        const float* Kg = Kf + (((size_t)(b * SS + k0)) * HH + h) * QKHD;
        #pragma unroll
        for (int n = 0; n < 12; n++) {
            int i = tid + n * 256;
            int r = i / 48, d4 = (i % 48) * 4;
            float4 v = *(const float4*)&Kg[(size_t)r * (HH * QKHD) + d4];
            v.x = f2tf32f(v.x); v.y = f2tf32f(v.y);
            v.z = f2tf32f(v.z); v.w = f2tf32f(v.w);
            *(float4*)&Ks[r * KSP + d4] = v;
        }
        const float* Vg = V + (((size_t)(b * SS + k0)) * HH + h) * VHD;
        #pragma unroll
        for (int n = 0; n < 8; n++) {
            int i = tid + n * 256;
            int r = i / 32, d4 = (i % 32) * 4;
            float4 v = *(const float4*)&Vg[(size_t)r * (HH * VHD) + d4];
            v.x = f2tf32f(v.x); v.y = f2tf32f(v.y);
            v.z = f2tf32f(v.z); v.w = f2tf32f(v.w);
            *(float4*)&Vs[r * VSP + d4] = v;
        }
        __syncthreads();

        float sc[4][4];
        #pragma unroll
        for (int nt = 0; nt < 4; nt++)
            #pragma unroll
            for (int i = 0; i < 4; i++) sc[nt][i] = 0.f;

        #pragma unroll
        for (int kc = 0; kc < 24; kc++) {
            uint32_t af[4];
            af[0] = __float_as_uint(Qs[rA * QSP + kc * 8 + tg]);
            af[1] = __float_as_uint(Qs[(rA + 8) * QSP + kc * 8 + tg]);
            af[2] = __float_as_uint(Qs[rA * QSP + kc * 8 + tg + 4]);
            af[3] = __float_as_uint(Qs[(rA + 8) * QSP + kc * 8 + tg + 4]);
            #pragma unroll
            for (int nt = 0; nt < 4; nt++) {
                int kvr = kh * 32 + nt * 8 + g;
                uint32_t bf[2];
                bf[0] = __float_as_uint(Ks[kvr * KSP + kc * 8 + tg]);
                bf[1] = __float_as_uint(Ks[kvr * KSP + kc * 8 + tg + 4]);
                mma_tf32(sc[nt], af, bf);
            }
        }

        if (j == jend) {
            #pragma unroll
            for (int nt = 0; nt < 4; nt++) {
                int colb = k0 + kh * 32 + nt * 8 + 2 * tg;
                int row0g = q0 + rA, row1g = q0 + rA + 8;
                if (colb     > row0g) sc[nt][0] = -INFINITY;
                if (colb + 1 > row0g) sc[nt][1] = -INFINITY;
                if (colb     > row1g) sc[nt][2] = -INFINITY;
                if (colb + 1 > row1g) sc[nt][3] = -INFINITY;
            }
        }

        float ml0 = -INFINITY, ml1 = -INFINITY;
        #pragma unroll
        for (int nt = 0; nt < 4; nt++) {
            ml0 = fmaxf(ml0, fmaxf(sc[nt][0], sc[nt][1]));
            ml1 = fmaxf(ml1, fmaxf(sc[nt][2], sc[nt][3]));
        }
        ml0 = fmaxf(ml0, __shfl_xor_sync(0xffffffffu, ml0, 1));
        ml0 = fmaxf(ml0, __shfl_xor_sync(0xffffffffu, ml0, 2));
        ml1 = fmaxf(ml1, __shfl_xor_sync(0xffffffffu, ml1, 1));
        ml1 = fmaxf(ml1, __shfl_xor_sync(0xffffffffu, ml1, 2));
        float mn0 = fmaxf(m0, ml0), mn1 = fmaxf(m1, ml1);
        float mr0 = (mn0 == -INFINITY) ? 0.f : mn0;
        float mr1 = (mn1 == -INFINITY) ? 0.f : mn1;
        float a0 = __expf(m0 - mr0);
        float a1 = __expf(m1 - mr1);

        float ll0 = 0.f, ll1 = 0.f;
        #pragma unroll
        for (int nt = 0; nt < 4; nt++) {
            float p0 = __expf(sc[nt][0] - mr0);
            float p1 = __expf(sc[nt][1] - mr0);
            float p2 = __expf(sc[nt][2] - mr1);
            float p3 = __expf(sc[nt][3] - mr1);
            ll0 += p0 + p1;
            ll1 += p2 + p3;
            int cb = kh * 32 + nt * 8 + 2 * tg;
            *(float2*)&Ps[rA * PSP + cb]       = make_float2(f2tf32f(p0), f2tf32f(p1));
            *(float2*)&Ps[(rA + 8) * PSP + cb] = make_float2(f2tf32f(p2), f2tf32f(p3));
        }
        ll0 += __shfl_xor_sync(0xffffffffu, ll0, 1);
        ll0 += __shfl_xor_sync(0xffffffffu, ll0, 2);
        ll1 += __shfl_xor_sync(0xffffffffu, ll1, 1);
        ll1 += __shfl_xor_sync(0xffffffffu, ll1, 2);

        m0 = mn0; m1 = mn1;
        l0 = l0 * a0 + ll0;
        l1 = l1 * a1 + ll1;

        #pragma unroll
        for (int nt = 0; nt < 16; nt++) {
            acc[nt][0] *= a0; acc[nt][1] *= a0;
            acc[nt][2] *= a1; acc[nt][3] *= a1;
        }
        __syncwarp();

        #pragma unroll
        for (int kc = 0; kc < 4; kc++) {
            uint32_t af[4];
            int pc = kh * 32 + kc * 8;
            af[0] = __float_as_uint(Ps[rA * PSP + pc + tg]);
            af[1] = __float_as_uint(Ps[(rA + 8) * PSP + pc + tg]);
            af[2] = __float_as_uint(Ps[rA * PSP + pc + tg + 4]);
            af[3] = __float_as_uint(Ps[(rA + 8) * PSP + pc + tg + 4]);
            int kv0 = kh * 32 + kc * 8 + tg;
            #pragma unroll
            for (int nt = 0; nt < 16; nt++) {
                uint32_t bf[2];
                bf[0] = __float_as_uint(Vs[kv0 * VSP + nt * 8 + g]);
                bf[1] = __float_as_uint(Vs[(kv0 + 4) * VSP + nt * 8 + g]);
                mma_tf32(acc[nt], af, bf);
            }
        }
        __syncwarp();
    }

    // ---- merge kv halves, write tf32-rounded O (feeds o-proj GEMM) ----
    __syncthreads();
    float* Osh = Ks;
    float* msh = Ps;
    float* lsh = Ps + 64;

    if (kh == 1) {
        if (tg == 0) {
            msh[rA] = m0;  msh[rA + 8] = m1;
            lsh[rA] = l0;  lsh[rA + 8] = l1;
        }
        #pragma unroll
        for (int nt = 0; nt < 16; nt++) {
            int cb = nt * 8 + 2 * tg;
            *(float2*)&Osh[rA * OSP + cb]       = make_float2(acc[nt][0], acc[nt][1]);
            *(float2*)&Osh[(rA + 8) * OSP + cb] = make_float2(acc[nt][2], acc[nt][3]);
        }
    }
    __syncthreads();
    if (kh == 0) {
        float mB0 = msh[rA], mB1 = msh[rA + 8];
        float lB0 = lsh[rA], lB1 = lsh[rA + 8];
        float mm0 = fmaxf(m0, mB0), mm1 = fmaxf(m1, mB1);
        float wA0 = __expf(m0 - mm0),  wB0 = __expf(mB0 - mm0);
        float wA1 = __expf(m1 - mm1),  wB1 = __expf(mB1 - mm1);
        float inv0 = 1.f / (wA0 * l0 + wB0 * lB0);
        float inv1 = 1.f / (wA1 * l1 + wB1 * lB1);

        size_t ob0 = (((size_t)(b * SS + q0 + rA)) * HH + h) * VHD;
        size_t ob1 = (((size_t)(b * SS + q0 + rA + 8)) * HH + h) * VHD;
        #pragma unroll
        for (int nt = 0; nt < 16; nt++) {
            int cb = nt * 8 + 2 * tg;
            float2 oB0 = *(float2*)&Osh[rA * OSP + cb];
            float2 oB1 = *(float2*)&Osh[(rA + 8) * OSP + cb];
            float2 r0, r1;
            r0.x = f2tf32f((wA0 * acc[nt][0] + wB0 * oB0.x) * inv0);
            r0.y = f2tf32f((wA0 * acc[nt][1] + wB0 * oB0.y) * inv0);
            r1.x = f2tf32f((wA1 * acc[nt][2] + wB1 * oB1.x) * inv1);
            r1.y = f2tf32f((wA1 * acc[nt][3] + wB1 * oB1.y) * inv1);
            *(float2*)&O[ob0 + cb] = r0;
            *(float2*)&O[ob1 + cb] = r1;
        }
    }
}

// ---------------- launch -----------------------------------------------------
extern "C" void kernel_launch(void* const* d_in, const int* in_sizes, int n_in,
                              void* d_out, int out_size)
{
    const float* x       = (const float*)d_in[0];
    const float* wq_w    = (const float*)d_in[1];
    const float* wq_b    = (const float*)d_in[2];
    const float* wkv_a_w = (const float*)d_in[3];
    const float* wkv_a_b = (const float*)d_in[4];
    const float* kvn_g   = (const float*)d_in[5];
    const float* kvn_b   = (const float*)d_in[6];
    const float* wk_w    = (const float*)d_in[7];
    const float* wk_b    = (const float*)d_in[8];
    const float* wv_w    = (const float*)d_in[9];
    const float* wv_b    = (const float*)d_in[10];
    const float* wo_w    = (const float*)d_in[11];
    const float* wo_b    = (const float*)d_in[12];
    const float* cosT    = (const float*)d_in[13];
    const float* sinT    = (const float*)d_in[14];
    float* out = (float*)d_out;

    float *gq, *gkv, *gc, *gkn, *gv, *gK, *gO;
    float *xt, *wqt, *wkvt, *wkt, *wvt, *wot;
    cudaGetSymbolAddress((void**)&gq,   g_q);
    cudaGetSymbolAddress((void**)&gkv,  g_kv);
    cudaGetSymbolAddress((void**)&gc,   g_c);
    cudaGetSymbolAddress((void**)&gkn,  g_kn);
    cudaGetSymbolAddress((void**)&gv,   g_v);
    cudaGetSymbolAddress((void**)&gK,   g_K);
    cudaGetSymbolAddress((void**)&gO,   g_O);
    cudaGetSymbolAddress((void**)&xt,   g_xt);
    cudaGetSymbolAddress((void**)&wqt,  g_wqt);
    cudaGetSymbolAddress((void**)&wkvt, g_wkvt);
    cudaGetSymbolAddress((void**)&wkt,  g_wkt);
    cudaGetSymbolAddress((void**)&wvt,  g_wvt);
    cudaGetSymbolAddress((void**)&wot,  g_wot);

    cudaFuncSetAttribute(gemm_tf32_kernel, cudaFuncAttributeMaxDynamicSharedMemorySize, (int)GEMM_SMEM);
    cudaFuncSetAttribute(attn_mma_kernel, cudaFuncAttributeMaxDynamicSharedMemorySize, (int)ATTN_SMEM);

    // 0) tf32 round all GEMM operands
    {
        struct { const float* s; float* d; int n; } cv[6] = {
            { x,       xt,   ROWS * DIM },
            { wq_w,    wqt,  DIM * QCOLS },
            { wkv_a_w, wkvt, DIM * KVCOLS },
            { wk_w,    wkt,  KVRANK * HH * NOPE },
            { wv_w,    wvt,  KVRANK * HH * VHD },
            { wo_w,    wot,  HH * VHD * DIM },
        };
        for (int i = 0; i < 6; i++) {
            int n4 = cv[i].n / 4;
            tf32_convert_kernel<<<(n4 + 255) / 256, 256>>>(cv[i].s, cv[i].d, n4);
        }
    }

    // 1) q = x @ wq_w + b
    gemm_tf32_kernel<<<dim3(QCOLS/GBN, ROWS/GBM), 256, GEMM_SMEM>>>(xt, wqt, wq_b, gq, ROWS, QCOLS, DIM);
    // 2) kv = x @ wkv_a_w + b
    gemm_tf32_kernel<<<dim3(KVCOLS/GBN, ROWS/GBM), 256, GEMM_SMEM>>>(xt, wkvt, wkv_a_b, gkv, ROWS, KVCOLS, DIM);
    // 3) layernorm latent (tf32-rounded output)
    ln_kernel<<<ROWS, 128>>>(gkv, kvn_g, kvn_b, gc);
    // 4) k_nope = c @ wk_w + b
    gemm_tf32_kernel<<<dim3((HH*NOPE)/GBN, ROWS/GBM), 256, GEMM_SMEM>>>(gc, wkt, wk_b, gkn, ROWS, HH*NOPE, KVRANK);
    // 5) v = c @ wv_w + b
    gemm_tf32_kernel<<<dim3((HH*VHD)/GBN, ROWS/GBM), 256, GEMM_SMEM>>>(gc, wvt, wv_b, gv, ROWS, HH*VHD, KVRANK);
    // 6) rope + assemble K
    {
        int total = ROWS * HH * 32;
        rope_assemble_kernel<<<(total + 255) / 256, 256>>>(gq, gkv, gkn, cosT, sinT, gK);
    }
    // 7) attention (tf32 tensor cores; emits tf32-rounded O)
    attn_mma_kernel<<<dim3(SS/ABQ, HH, BB), 256, ATTN_SMEM>>>(gq, gK, gv, gO);
    // 8) out = O @ wo_w + b
    gemm_tf32_kernel<<<dim3(DIM/GBN, ROWS/GBM), 256, GEMM_SMEM>>>(gO, wot, wo_b, out, ROWS, DIM, HH*VHD);
}